// round 4
// baseline (speedup 1.0000x reference)
#include <cuda_runtime.h>
#include <math.h>

#define BLOCK 256

// ---- dims ----
// 168 -> 84 -> 42 -> 21 -> 12 -> 10 -> 5 -> 2 -> 1

// ---- smem layout (float offsets), each segment padded to 4-float alignment ----
#define OFF_W1 0        // 14112
#define OFF_B1 14112    // 84
#define OFF_W2 14196    // 3528
#define OFF_B2 17724    // 42   (ends 17766)
#define OFF_W3 17768    // 882  (ends 18650)
#define OFF_B3 18652    // 21   (ends 18673)
#define OFF_W4 18676    // 252
#define OFF_B4 18928    // 12
#define OFF_W5 18940    // 120
#define OFF_B5 19060    // 10   (ends 19070)
#define OFF_W6 19072    // 50   (ends 19122)
#define OFF_B6 19124    // 5    (ends 19129)
#define OFF_W7 19132    // 10
#define OFF_B7 19144    // 2
#define OFF_W8 19148    // 2
#define OFF_B8 19152    // 1
#define SMEM_FLOATS 19156
#define SMEM_BYTES (SMEM_FLOATS * 4)

__device__ __forceinline__ void copy_smem(float* dst, const float* __restrict__ src, int n) {
    for (int i = threadIdx.x; i < n; i += BLOCK) dst[i] = src[i];
}

// Fully-unrolled dense layer: in[] / out[] are register arrays, weights broadcast from smem.
template<int IN, int OUT>
__device__ __forceinline__ void dense_relu(const float* __restrict__ sW,
                                           const float* __restrict__ sb,
                                           const float (&in)[IN], float (&out)[OUT]) {
#pragma unroll
    for (int j = 0; j < OUT; ++j) {
        float a = sb[j];
#pragma unroll
        for (int k = 0; k < IN; ++k) a = fmaf(in[k], sW[j * IN + k], a);
        out[j] = fmaxf(a, 0.0f);
    }
}

__global__ void __launch_bounds__(BLOCK, 1) mlp_kernel(
    const float* __restrict__ x,
    const float* __restrict__ W1, const float* __restrict__ b1,
    const float* __restrict__ W2, const float* __restrict__ b2,
    const float* __restrict__ W3, const float* __restrict__ b3,
    const float* __restrict__ W4, const float* __restrict__ b4,
    const float* __restrict__ W5, const float* __restrict__ b5,
    const float* __restrict__ W6, const float* __restrict__ b6,
    const float* __restrict__ W7, const float* __restrict__ b7,
    const float* __restrict__ W8, const float* __restrict__ b8,
    float* __restrict__ out, int batch)
{
    extern __shared__ float s[];
    copy_smem(s + OFF_W1, W1, 14112);
    copy_smem(s + OFF_B1, b1, 84);
    copy_smem(s + OFF_W2, W2, 3528);
    copy_smem(s + OFF_B2, b2, 42);
    copy_smem(s + OFF_W3, W3, 882);
    copy_smem(s + OFF_B3, b3, 21);
    copy_smem(s + OFF_W4, W4, 252);
    copy_smem(s + OFF_B4, b4, 12);
    copy_smem(s + OFF_W5, W5, 120);
    copy_smem(s + OFF_B5, b5, 10);
    copy_smem(s + OFF_W6, W6, 50);
    copy_smem(s + OFF_B6, b6, 5);
    copy_smem(s + OFF_W7, W7, 10);
    copy_smem(s + OFF_B7, b7, 2);
    copy_smem(s + OFF_W8, W8, 2);
    copy_smem(s + OFF_B8, b8, 1);
    __syncthreads();

    int row = blockIdx.x * BLOCK + threadIdx.x;
    if (row >= batch) return;

    // ---- layer 1: 168 -> 84 (x streamed from gmem in float4 chunks) ----
    float a1[84];
    {
        const float* sb1 = s + OFF_B1;
#pragma unroll
        for (int j = 0; j < 84; ++j) a1[j] = sb1[j];

        const float4* xr = reinterpret_cast<const float4*>(x + (size_t)row * 168);
        const float* sW1 = s + OFF_W1;
        for (int c = 0; c < 42; ++c) {   // rolled: keeps I$ footprint sane
            float4 xv = __ldg(&xr[c]);
#pragma unroll
            for (int j = 0; j < 84; ++j) {
                float4 wv = *reinterpret_cast<const float4*>(&sW1[j * 168 + c * 4]);
                a1[j] = fmaf(xv.x, wv.x, a1[j]);
                a1[j] = fmaf(xv.y, wv.y, a1[j]);
                a1[j] = fmaf(xv.z, wv.z, a1[j]);
                a1[j] = fmaf(xv.w, wv.w, a1[j]);
            }
        }
#pragma unroll
        for (int j = 0; j < 84; ++j) a1[j] = fmaxf(a1[j], 0.0f);
    }

    // ---- layers 2..7 in registers ----
    float a2[42]; dense_relu<84, 42>(s + OFF_W2, s + OFF_B2, a1, a2);
    float a3[21]; dense_relu<42, 21>(s + OFF_W3, s + OFF_B3, a2, a3);
    float a4[12]; dense_relu<21, 12>(s + OFF_W4, s + OFF_B4, a3, a4);
    float a5[10]; dense_relu<12, 10>(s + OFF_W5, s + OFF_B5, a4, a5);
    float a6[5];  dense_relu<10, 5>(s + OFF_W6, s + OFF_B6, a5, a6);
    float a7[2];  dense_relu<5, 2>(s + OFF_W7, s + OFF_B7, a6, a7);

    // ---- layer 8: 2 -> 1 + sigmoid ----
    float z = s[OFF_B8];
    z = fmaf(a7[0], s[OFF_W8 + 0], z);
    z = fmaf(a7[1], s[OFF_W8 + 1], z);
    out[row] = 1.0f / (1.0f + expf(-z));
}

extern "C" void kernel_launch(void* const* d_in, const int* in_sizes, int n_in,
                              void* d_out, int out_size) {
    const float* x  = (const float*)d_in[0];
    const float* W1 = (const float*)d_in[1];
    const float* b1 = (const float*)d_in[2];
    const float* W2 = (const float*)d_in[3];
    const float* b2 = (const float*)d_in[4];
    const float* W3 = (const float*)d_in[5];
    const float* b3 = (const float*)d_in[6];
    const float* W4 = (const float*)d_in[7];
    const float* b4 = (const float*)d_in[8];
    const float* W5 = (const float*)d_in[9];
    const float* b5 = (const float*)d_in[10];
    const float* W6 = (const float*)d_in[11];
    const float* b6 = (const float*)d_in[12];
    const float* W7 = (const float*)d_in[13];
    const float* b7 = (const float*)d_in[14];
    const float* W8 = (const float*)d_in[15];
    const float* b8 = (const float*)d_in[16];
    float* out = (float*)d_out;

    int batch = in_sizes[0] / 168;

    cudaFuncSetAttribute(mlp_kernel, cudaFuncAttributeMaxDynamicSharedMemorySize, SMEM_BYTES);

    int grid = (batch + BLOCK - 1) / BLOCK;
    mlp_kernel<<<grid, BLOCK, SMEM_BYTES>>>(
        x, W1, b1, W2, b2, W3, b3, W4, b4, W5, b5, W6, b6, W7, b7, W8, b8,
        out, batch);
}

// round 6
// speedup vs baseline: 2.2352x; 2.2352x over previous
#include <cuda_runtime.h>
#include <cuda_bf16.h>
#include <math.h>
#include <stdint.h>

// ============================================================================
// Fused 8-layer MLP 168->84->42->21->12->10->5->2->1, batch 262144.
// Layers 1-2: warp-level mma.sync bf16 (3-pass hi/lo split, fp32 accum).
// Layers 3-8: scalar fp32 per thread. Weight fragments precomputed by prep
// kernel in exact mma lane layout (base sm_100 PTX only — no tcgen05).
// ============================================================================

#define THREADS 256

// mma tile counts
#define L1_NT 11   // n-tiles of 8  (88 >= 84)
#define L1_KT 11   // k-steps of 16 (176 >= 168)
#define L2_NT 6    // 48 >= 42
#define L2_KT 6    // 96 >= 84

// fragment image sizes (uint32 each; 2 regs per lane per frag)
#define FR1 (L1_NT * L1_KT * 32 * 2)    // 7744
#define FR2 (L2_NT * L2_KT * 32 * 2)    // 2304
#define FR_TOTAL_U32 (2 * FR1 + 2 * FR2)  // 20096

// aux float layout
#define X_B1 0
#define X_B2 84
#define X_W3 126
#define X_B3 1008
#define X_W4 1029
#define X_B4 1281
#define X_W5 1293
#define X_B5 1413
#define X_W6 1423
#define X_B6 1473
#define X_W7 1478
#define X_B7 1488
#define X_W8 1490
#define X_B8 1492
#define AUX_N 1493

// smem layout (bytes)
#define OFF_B1HI 0
#define OFF_B1LO (OFF_B1HI + FR1 * 4)        // 30976
#define OFF_B2HI (OFF_B1LO + FR1 * 4)        // 61952
#define OFF_B2LO (OFF_B2HI + FR2 * 4)        // 71168
#define OFF_AUX  (OFF_B2LO + FR2 * 4)        // 80384
#define OFF_A2   (((OFF_AUX + AUX_N * 4) + 15) & ~15)   // 86368
#define A2_STRIDE 43
#define SMEM_TOTAL (OFF_A2 + 256 * A2_STRIDE * 4)       // 130400

// ---------------- device globals ----------------
__device__ __align__(16) uint32_t g_fr[FR_TOTAL_U32];
__device__ __align__(16) float g_aux[AUX_N + 3];

// ---------------- helpers ----------------
__device__ __forceinline__ uint32_t pack_bf2(float f0, float f1) {
    // result: lo half = bf16(f0), hi half = bf16(f1)
    uint32_t r;
    asm("cvt.rn.bf16x2.f32 %0, %1, %2;" : "=r"(r) : "f"(f1), "f"(f0));
    return r;
}
__device__ __forceinline__ uint32_t pack_lo_residual(float f0, float f1, uint32_t hi) {
    float r0 = __uint_as_float(hi << 16);
    float r1 = __uint_as_float(hi & 0xFFFF0000u);
    return pack_bf2(f0 - r0, f1 - r1);
}

#define MMA_BF16(c, a0, a1, a2, a3, b0, b1) \
    asm volatile("mma.sync.aligned.m16n8k16.row.col.f32.bf16.bf16.f32 " \
        "{%0,%1,%2,%3}, {%4,%5,%6,%7}, {%8,%9}, {%0,%1,%2,%3};" \
        : "+f"((c)[0]), "+f"((c)[1]), "+f"((c)[2]), "+f"((c)[3]) \
        : "r"(a0), "r"(a1), "r"(a2), "r"(a3), "r"(b0), "r"(b1))

template<int IN, int OUT>
__device__ __forceinline__ void dense_relu(const float* __restrict__ sW,
                                           const float* __restrict__ sb,
                                           const float (&in)[IN], float (&out)[OUT]) {
#pragma unroll
    for (int j = 0; j < OUT; ++j) {
        float a = sb[j];
#pragma unroll
        for (int k = 0; k < IN; ++k) a = fmaf(in[k], sW[j * IN + k], a);
        out[j] = fmaxf(a, 0.0f);
    }
}

// ---------------- prep kernel: build B fragments + aux ----------------
// m16n8k16 .row.col B fragment layout (lane = 4*g_cols? no: g = lane>>2, i = lane&3):
//   reg0 = { B[k=16t+2i][n=8j+g], B[k=16t+2i+1][n] }  (lo half = lower k)
//   reg1 = same with k += 8
// where B[k][n] = W[n][k].
__global__ void prep_kernel(
    const float* __restrict__ W1, const float* __restrict__ b1,
    const float* __restrict__ W2, const float* __restrict__ b2,
    const float* __restrict__ W3, const float* __restrict__ b3,
    const float* __restrict__ W4, const float* __restrict__ b4,
    const float* __restrict__ W5, const float* __restrict__ b5,
    const float* __restrict__ W6, const float* __restrict__ b6,
    const float* __restrict__ W7, const float* __restrict__ b7,
    const float* __restrict__ W8, const float* __restrict__ b8)
{
    int tid = blockIdx.x * blockDim.x + threadIdx.x;
    int stride = gridDim.x * blockDim.x;

    // layer-1 fragments: fs in [0, 11*11*32)
    for (int fs = tid; fs < L1_NT * L1_KT * 32; fs += stride) {
        int j = fs / (L1_KT * 32);
        int rem = fs % (L1_KT * 32);
        int t = rem / 32;
        int lane = rem % 32;
        int g = lane >> 2, i = lane & 3;
        int n = 8 * j + g;
#pragma unroll
        for (int r = 0; r < 2; ++r) {
            int k0 = 16 * t + 8 * r + 2 * i;
            float w0 = (n < 84 && k0     < 168) ? W1[n * 168 + k0]     : 0.0f;
            float w1v = (n < 84 && k0 + 1 < 168) ? W1[n * 168 + k0 + 1] : 0.0f;
            __nv_bfloat16 h0 = __float2bfloat16(w0), h1 = __float2bfloat16(w1v);
            float hf0 = __bfloat162float(h0), hf1 = __bfloat162float(h1);
            __nv_bfloat16 l0 = __float2bfloat16(w0 - hf0), l1 = __float2bfloat16(w1v - hf1);
            uint32_t hi = ((uint32_t)__bfloat16_as_ushort(h1) << 16) | __bfloat16_as_ushort(h0);
            uint32_t lo = ((uint32_t)__bfloat16_as_ushort(l1) << 16) | __bfloat16_as_ushort(l0);
            g_fr[OFF_B1HI / 4 + fs * 2 + r] = hi;
            g_fr[OFF_B1LO / 4 + fs * 2 + r] = lo;
        }
    }
    // layer-2 fragments: fs in [0, 6*6*32)
    for (int fs = tid; fs < L2_NT * L2_KT * 32; fs += stride) {
        int j = fs / (L2_KT * 32);
        int rem = fs % (L2_KT * 32);
        int t = rem / 32;
        int lane = rem % 32;
        int g = lane >> 2, i = lane & 3;
        int n = 8 * j + g;
#pragma unroll
        for (int r = 0; r < 2; ++r) {
            int k0 = 16 * t + 8 * r + 2 * i;
            float w0 = (n < 42 && k0     < 84) ? W2[n * 84 + k0]     : 0.0f;
            float w1v = (n < 42 && k0 + 1 < 84) ? W2[n * 84 + k0 + 1] : 0.0f;
            __nv_bfloat16 h0 = __float2bfloat16(w0), h1 = __float2bfloat16(w1v);
            float hf0 = __bfloat162float(h0), hf1 = __bfloat162float(h1);
            __nv_bfloat16 l0 = __float2bfloat16(w0 - hf0), l1 = __float2bfloat16(w1v - hf1);
            uint32_t hi = ((uint32_t)__bfloat16_as_ushort(h1) << 16) | __bfloat16_as_ushort(h0);
            uint32_t lo = ((uint32_t)__bfloat16_as_ushort(l1) << 16) | __bfloat16_as_ushort(l0);
            g_fr[OFF_B2HI / 4 + fs * 2 + r] = hi;
            g_fr[OFF_B2LO / 4 + fs * 2 + r] = lo;
        }
    }
    // aux table
    for (int i = tid; i < AUX_N; i += stride) {
        float v;
        if      (i < X_B2)  v = b1[i - X_B1];
        else if (i < X_W3)  v = b2[i - X_B2];
        else if (i < X_B3)  v = W3[i - X_W3];
        else if (i < X_W4)  v = b3[i - X_B3];
        else if (i < X_B4)  v = W4[i - X_W4];
        else if (i < X_W5)  v = b4[i - X_B4];
        else if (i < X_B5)  v = W5[i - X_W5];
        else if (i < X_W6)  v = b5[i - X_B5];
        else if (i < X_B6)  v = W6[i - X_W6];
        else if (i < X_W7)  v = b6[i - X_B6];
        else if (i < X_B7)  v = W7[i - X_W7];
        else if (i < X_W8)  v = b7[i - X_B7];
        else if (i < X_B8)  v = W8[i - X_W8];
        else                v = b8[0];
        g_aux[i] = v;
    }
}

// ---------------- main kernel ----------------
// grid = batch/256 CTAs; CTA handles rows [b*256, b*256+256) as two 128-row
// tiles (8 warps x 16 rows each).
__global__ void __launch_bounds__(THREADS) mlp_mma_kernel(
    const float* __restrict__ x, float* __restrict__ out)
{
    extern __shared__ __align__(16) unsigned char smem[];
    int tid = threadIdx.x;
    int warp = tid >> 5;
    int lane = tid & 31;
    int g = lane >> 2, i = lane & 3;

    // fill smem: fragment images + aux
    {
        const uint4* src = (const uint4*)g_fr;
        uint4* dst = (uint4*)smem;
        for (int q = tid; q < (FR_TOTAL_U32 * 4) / 16; q += THREADS) dst[q] = src[q];
        float* sa = (float*)(smem + OFF_AUX);
        for (int q = tid; q < AUX_N; q += THREADS) sa[q] = g_aux[q];
    }
    __syncthreads();

    const uint2* B1h = (const uint2*)(smem + OFF_B1HI);
    const uint2* B1l = (const uint2*)(smem + OFF_B1LO);
    const uint2* B2h = (const uint2*)(smem + OFF_B2HI);
    const uint2* B2l = (const uint2*)(smem + OFF_B2LO);
    const float* sAux = (const float*)(smem + OFF_AUX);
    float* a2buf = (float*)(smem + OFF_A2);

    for (int ph = 0; ph < 2; ++ph) {
        int rowA = blockIdx.x * 256 + ph * 128 + warp * 16 + g;   // global row (and +8)
        const float* xr0 = x + (size_t)rowA * 168;
        const float* xr1 = xr0 + 8 * 168;

        // ================= layer 1: mma over K=176, N=88 =================
        float acc[L1_NT][4];
#pragma unroll
        for (int j = 0; j < L1_NT; ++j) {
            acc[j][0] = 0.f; acc[j][1] = 0.f; acc[j][2] = 0.f; acc[j][3] = 0.f;
        }

        for (int t = 0; t < L1_KT; ++t) {
            int c0 = 16 * t + 2 * i;          // low-k pair col
            int c1 = c0 + 8;                  // high-k pair col
            float2 va = *(const float2*)(xr0 + c0);
            float2 vb = *(const float2*)(xr1 + c0);
            float2 vc, vd;
            if (c1 < 167) {                   // t<10 always true; t==10 -> c1>=168
                vc = *(const float2*)(xr0 + c1);
                vd = *(const float2*)(xr1 + c1);
            } else {
                vc = make_float2(0.f, 0.f); vd = make_float2(0.f, 0.f);
            }
            uint32_t a0h = pack_bf2(va.x, va.y), a1h = pack_bf2(vb.x, vb.y);
            uint32_t a2h = pack_bf2(vc.x, vc.y), a3h = pack_bf2(vd.x, vd.y);
            uint32_t a0l = pack_lo_residual(va.x, va.y, a0h);
            uint32_t a1l = pack_lo_residual(vb.x, vb.y, a1h);
            uint32_t a2l = pack_lo_residual(vc.x, vc.y, a2h);
            uint32_t a3l = pack_lo_residual(vd.x, vd.y, a3h);

#pragma unroll
            for (int j = 0; j < L1_NT; ++j) {
                uint2 bh = B1h[(j * L1_KT + t) * 32 + lane];
                uint2 bl = B1l[(j * L1_KT + t) * 32 + lane];
                MMA_BF16(acc[j], a0h, a1h, a2h, a3h, bh.x, bh.y);   // hi*hi
                MMA_BF16(acc[j], a0l, a1l, a2l, a3l, bh.x, bh.y);   // lo*hi
                MMA_BF16(acc[j], a0h, a1h, a2h, a3h, bl.x, bl.y);   // hi*lo
            }
        }

        // ============ epilogue 1: bias + relu (in fragment layout) ============
#pragma unroll
        for (int j = 0; j < L1_NT; ++j) {
            int col0 = 8 * j + 2 * i, col1 = col0 + 1;
            float bb0 = (col0 < 84) ? sAux[X_B1 + col0] : 0.0f;
            float bb1 = (col1 < 84) ? sAux[X_B1 + col1] : 0.0f;
            acc[j][0] = fmaxf(acc[j][0] + bb0, 0.0f);
            acc[j][1] = fmaxf(acc[j][1] + bb1, 0.0f);
            acc[j][2] = fmaxf(acc[j][2] + bb0, 0.0f);
            acc[j][3] = fmaxf(acc[j][3] + bb1, 0.0f);
        }

        // ======= build layer-2 A fragments in registers (no shuffles) =======
        // A2 kstep s: a0 = C(ntile 2s).{c0,c1}, a1 = C(2s).{c2,c3},
        //             a2 = C(2s+1).{c0,c1},     a3 = C(2s+1).{c2,c3}
        uint32_t a2f_hi[L2_KT][4], a2f_lo[L2_KT][4];
#pragma unroll
        for (int s = 0; s < L2_KT; ++s) {
            int jA = 2 * s, jB = 2 * s + 1;
            float fA0 = acc[jA][0], fA1 = acc[jA][1], fA2 = acc[jA][2], fA3 = acc[jA][3];
            float fB0 = 0.f, fB1 = 0.f, fB2 = 0.f, fB3 = 0.f;
            if (jB < L1_NT) { fB0 = acc[jB][0]; fB1 = acc[jB][1]; fB2 = acc[jB][2]; fB3 = acc[jB][3]; }
            a2f_hi[s][0] = pack_bf2(fA0, fA1);
            a2f_hi[s][1] = pack_bf2(fA2, fA3);
            a2f_hi[s][2] = pack_bf2(fB0, fB1);
            a2f_hi[s][3] = pack_bf2(fB2, fB3);
            a2f_lo[s][0] = pack_lo_residual(fA0, fA1, a2f_hi[s][0]);
            a2f_lo[s][1] = pack_lo_residual(fA2, fA3, a2f_hi[s][1]);
            a2f_lo[s][2] = pack_lo_residual(fB0, fB1, a2f_hi[s][2]);
            a2f_lo[s][3] = pack_lo_residual(fB2, fB3, a2f_hi[s][3]);
        }

        // ================= layer 2: mma over K=96, N=48 =================
        float acc2[L2_NT][4];
#pragma unroll
        for (int j = 0; j < L2_NT; ++j) {
            acc2[j][0] = 0.f; acc2[j][1] = 0.f; acc2[j][2] = 0.f; acc2[j][3] = 0.f;
        }
#pragma unroll
        for (int s = 0; s < L2_KT; ++s) {
#pragma unroll
            for (int j = 0; j < L2_NT; ++j) {
                uint2 bh = B2h[(j * L2_KT + s) * 32 + lane];
                uint2 bl = B2l[(j * L2_KT + s) * 32 + lane];
                MMA_BF16(acc2[j], a2f_hi[s][0], a2f_hi[s][1], a2f_hi[s][2], a2f_hi[s][3], bh.x, bh.y);
                MMA_BF16(acc2[j], a2f_lo[s][0], a2f_lo[s][1], a2f_lo[s][2], a2f_lo[s][3], bh.x, bh.y);
                MMA_BF16(acc2[j], a2f_hi[s][0], a2f_hi[s][1], a2f_hi[s][2], a2f_hi[s][3], bl.x, bl.y);
            }
        }

        // ====== epilogue 2: bias + relu -> a2buf (stride 43, no conflicts) ======
        {
            int slot0 = ph * 128 + warp * 16 + g;       // rows g / g+8
            int slot1 = slot0 + 8;
#pragma unroll
            for (int j = 0; j < L2_NT; ++j) {
                int col0 = 8 * j + 2 * i, col1 = col0 + 1;
                if (col0 < 42) {
                    float bb = sAux[X_B2 + col0];
                    a2buf[slot0 * A2_STRIDE + col0] = fmaxf(acc2[j][0] + bb, 0.0f);
                    a2buf[slot1 * A2_STRIDE + col0] = fmaxf(acc2[j][2] + bb, 0.0f);
                }
                if (col1 < 42) {
                    float bb = sAux[X_B2 + col1];
                    a2buf[slot0 * A2_STRIDE + col1] = fmaxf(acc2[j][1] + bb, 0.0f);
                    a2buf[slot1 * A2_STRIDE + col1] = fmaxf(acc2[j][3] + bb, 0.0f);
                }
            }
        }
    }

    __syncthreads();

    // ================= scalar tail: layers 3..8, one row per thread =================
    {
        float v[42];
#pragma unroll
        for (int k = 0; k < 42; ++k) v[k] = a2buf[tid * A2_STRIDE + k];

        float a3[21]; dense_relu<42, 21>(sAux + X_W3, sAux + X_B3, v,  a3);
        float a4[12]; dense_relu<21, 12>(sAux + X_W4, sAux + X_B4, a3, a4);
        float a5[10]; dense_relu<12, 10>(sAux + X_W5, sAux + X_B5, a4, a5);
        float a6[5];  dense_relu<10, 5>(sAux + X_W6, sAux + X_B6, a5, a6);
        float a7[2];  dense_relu<5, 2>(sAux + X_W7, sAux + X_B7, a6, a7);

        float z = sAux[X_B8];
        z = fmaf(a7[0], sAux[X_W8 + 0], z);
        z = fmaf(a7[1], sAux[X_W8 + 1], z);
        out[blockIdx.x * 256 + tid] = 1.0f / (1.0f + expf(-z));
    }
}

// ---------------- launch ----------------
extern "C" void kernel_launch(void* const* d_in, const int* in_sizes, int n_in,
                              void* d_out, int out_size) {
    const float* x  = (const float*)d_in[0];
    const float* W1 = (const float*)d_in[1];
    const float* b1 = (const float*)d_in[2];
    const float* W2 = (const float*)d_in[3];
    const float* b2 = (const float*)d_in[4];
    const float* W3 = (const float*)d_in[5];
    const float* b3 = (const float*)d_in[6];
    const float* W4 = (const float*)d_in[7];
    const float* b4 = (const float*)d_in[8];
    const float* W5 = (const float*)d_in[9];
    const float* b5 = (const float*)d_in[10];
    const float* W6 = (const float*)d_in[11];
    const float* b6 = (const float*)d_in[12];
    const float* W7 = (const float*)d_in[13];
    const float* b7 = (const float*)d_in[14];
    const float* W8 = (const float*)d_in[15];
    const float* b8 = (const float*)d_in[16];
    float* out = (float*)d_out;

    int batch = in_sizes[0] / 168;
    int grid = batch / 256;

    prep_kernel<<<64, 256>>>(W1, b1, W2, b2, W3, b3, W4, b4,
                             W5, b5, W6, b6, W7, b7, W8, b8);

    cudaFuncSetAttribute(mlp_mma_kernel, cudaFuncAttributeMaxDynamicSharedMemorySize, SMEM_TOTAL);
    mlp_mma_kernel<<<grid, THREADS, SMEM_TOTAL>>>(x, out);
}

// round 7
// speedup vs baseline: 3.0235x; 1.3527x over previous
#include <cuda_runtime.h>
#include <cuda_bf16.h>
#include <math.h>
#include <stdint.h>

// ============================================================================
// Fused 8-layer MLP 168->84->42->21->12->10->5->2->1, batch 262144.
// Layers 1-2: warp-level mma.sync bf16 (3-pass hi/lo split, fp32 accum).
// Layers 3-8: scalar fp32 per thread.
// R6: 128 rows/CTA + interleaved hi/lo B frags (uint4) -> 2 CTAs/SM, half LDS.
// ============================================================================

#define THREADS 256

// mma tile counts
#define L1_NT 11   // n-tiles of 8  (88 >= 84)
#define L1_KT 11   // k-steps of 16 (176 >= 168)
#define L2_NT 6    // 48 >= 42
#define L2_KT 6    // 96 >= 84

// fragment image sizes in uint4 (one uint4 = {hi0, hi1, lo0, lo1})
#define FR1_U4 (L1_NT * L1_KT * 32)    // 3872
#define FR2_U4 (L2_NT * L2_KT * 32)    // 1152
#define FR_TOTAL_U4 (FR1_U4 + FR2_U4)  // 5024

// aux float layout
#define X_B1 0
#define X_B2 84
#define X_W3 126
#define X_B3 1008
#define X_W4 1029
#define X_B4 1281
#define X_W5 1293
#define X_B5 1413
#define X_W6 1423
#define X_B6 1473
#define X_W7 1478
#define X_B7 1488
#define X_W8 1490
#define X_B8 1492
#define AUX_N 1493

// smem layout (bytes)
#define OFF_B1   0
#define OFF_B2   (OFF_B1 + FR1_U4 * 16)          // 61952
#define OFF_AUX  (OFF_B2 + FR2_U4 * 16)          // 80384
#define OFF_A2   (((OFF_AUX + AUX_N * 4) + 15) & ~15)   // 86368
#define A2_STRIDE 43
#define ROWS_PER_CTA 128
#define SMEM_TOTAL (OFF_A2 + ROWS_PER_CTA * A2_STRIDE * 4)  // 108384

// ---------------- device globals ----------------
__device__ __align__(16) uint4 g_fr[FR_TOTAL_U4];
__device__ __align__(16) float g_aux[AUX_N + 3];

// ---------------- helpers ----------------
__device__ __forceinline__ uint32_t pack_bf2(float f0, float f1) {
    // result: lo half = bf16(f0), hi half = bf16(f1)
    uint32_t r;
    asm("cvt.rn.bf16x2.f32 %0, %1, %2;" : "=r"(r) : "f"(f1), "f"(f0));
    return r;
}
__device__ __forceinline__ uint32_t pack_lo_residual(float f0, float f1, uint32_t hi) {
    float r0 = __uint_as_float(hi << 16);
    float r1 = __uint_as_float(hi & 0xFFFF0000u);
    return pack_bf2(f0 - r0, f1 - r1);
}

#define MMA_BF16(c, a0, a1, a2, a3, b0, b1) \
    asm volatile("mma.sync.aligned.m16n8k16.row.col.f32.bf16.bf16.f32 " \
        "{%0,%1,%2,%3}, {%4,%5,%6,%7}, {%8,%9}, {%0,%1,%2,%3};" \
        : "+f"((c)[0]), "+f"((c)[1]), "+f"((c)[2]), "+f"((c)[3]) \
        : "r"(a0), "r"(a1), "r"(a2), "r"(a3), "r"(b0), "r"(b1))

template<int IN, int OUT>
__device__ __forceinline__ void dense_relu(const float* __restrict__ sW,
                                           const float* __restrict__ sb,
                                           const float (&in)[IN], float (&out)[OUT]) {
#pragma unroll
    for (int j = 0; j < OUT; ++j) {
        float a = sb[j];
#pragma unroll
        for (int k = 0; k < IN; ++k) a = fmaf(in[k], sW[j * IN + k], a);
        out[j] = fmaxf(a, 0.0f);
    }
}

// ---------------- prep kernel: build interleaved B fragments + aux ----------------
// m16n8k16 .row.col B fragment (g = lane>>2, i = lane&3), B[k][n] = W[n][k]:
//   reg0 = { B[16t+2i][8j+g], B[16t+2i+1][8j+g] }, reg1 = same with k += 8.
// uint4 image element (j*KT+t)*32+lane = { hi_reg0, hi_reg1, lo_reg0, lo_reg1 }.
__global__ void prep_kernel(
    const float* __restrict__ W1, const float* __restrict__ b1,
    const float* __restrict__ W2, const float* __restrict__ b2,
    const float* __restrict__ W3, const float* __restrict__ b3,
    const float* __restrict__ W4, const float* __restrict__ b4,
    const float* __restrict__ W5, const float* __restrict__ b5,
    const float* __restrict__ W6, const float* __restrict__ b6,
    const float* __restrict__ W7, const float* __restrict__ b7,
    const float* __restrict__ W8, const float* __restrict__ b8)
{
    int tid = blockIdx.x * blockDim.x + threadIdx.x;
    int stride = gridDim.x * blockDim.x;

    // layer-1 fragments
    for (int fs = tid; fs < FR1_U4; fs += stride) {
        int j = fs / (L1_KT * 32);
        int rem = fs % (L1_KT * 32);
        int t = rem / 32;
        int lane = rem % 32;
        int g = lane >> 2, i = lane & 3;
        int n = 8 * j + g;
        uint32_t hv[2], lv[2];
#pragma unroll
        for (int r = 0; r < 2; ++r) {
            int k0 = 16 * t + 8 * r + 2 * i;
            float w0 = (n < 84 && k0     < 168) ? W1[n * 168 + k0]     : 0.0f;
            float w1v = (n < 84 && k0 + 1 < 168) ? W1[n * 168 + k0 + 1] : 0.0f;
            __nv_bfloat16 h0 = __float2bfloat16(w0), h1 = __float2bfloat16(w1v);
            float hf0 = __bfloat162float(h0), hf1 = __bfloat162float(h1);
            __nv_bfloat16 l0 = __float2bfloat16(w0 - hf0), l1 = __float2bfloat16(w1v - hf1);
            hv[r] = ((uint32_t)__bfloat16_as_ushort(h1) << 16) | __bfloat16_as_ushort(h0);
            lv[r] = ((uint32_t)__bfloat16_as_ushort(l1) << 16) | __bfloat16_as_ushort(l0);
        }
        g_fr[fs] = make_uint4(hv[0], hv[1], lv[0], lv[1]);
    }
    // layer-2 fragments
    for (int fs = tid; fs < FR2_U4; fs += stride) {
        int j = fs / (L2_KT * 32);
        int rem = fs % (L2_KT * 32);
        int t = rem / 32;
        int lane = rem % 32;
        int g = lane >> 2, i = lane & 3;
        int n = 8 * j + g;
        uint32_t hv[2], lv[2];
#pragma unroll
        for (int r = 0; r < 2; ++r) {
            int k0 = 16 * t + 8 * r + 2 * i;
            float w0 = (n < 42 && k0     < 84) ? W2[n * 84 + k0]     : 0.0f;
            float w1v = (n < 42 && k0 + 1 < 84) ? W2[n * 84 + k0 + 1] : 0.0f;
            __nv_bfloat16 h0 = __float2bfloat16(w0), h1 = __float2bfloat16(w1v);
            float hf0 = __bfloat162float(h0), hf1 = __bfloat162float(h1);
            __nv_bfloat16 l0 = __float2bfloat16(w0 - hf0), l1 = __float2bfloat16(w1v - hf1);
            hv[r] = ((uint32_t)__bfloat16_as_ushort(h1) << 16) | __bfloat16_as_ushort(h0);
            lv[r] = ((uint32_t)__bfloat16_as_ushort(l1) << 16) | __bfloat16_as_ushort(l0);
        }
        g_fr[FR1_U4 + fs] = make_uint4(hv[0], hv[1], lv[0], lv[1]);
    }
    // aux table
    for (int i = tid; i < AUX_N; i += stride) {
        float v;
        if      (i < X_B2)  v = b1[i - X_B1];
        else if (i < X_W3)  v = b2[i - X_B2];
        else if (i < X_B3)  v = W3[i - X_W3];
        else if (i < X_W4)  v = b3[i - X_B3];
        else if (i < X_B4)  v = W4[i - X_W4];
        else if (i < X_W5)  v = b4[i - X_B4];
        else if (i < X_B5)  v = W5[i - X_W5];
        else if (i < X_W6)  v = b5[i - X_B5];
        else if (i < X_B6)  v = W6[i - X_W6];
        else if (i < X_W7)  v = b6[i - X_B6];
        else if (i < X_B7)  v = W7[i - X_W7];
        else if (i < X_W8)  v = b7[i - X_B7];
        else if (i < X_B8)  v = W8[i - X_W8];
        else                v = b8[0];
        g_aux[i] = v;
    }
}

// ---------------- main kernel ----------------
// grid = batch/128; CTA = 256 threads = 8 warps, each warp one m16 row-tile.
__global__ void __launch_bounds__(THREADS, 2) mlp_mma_kernel(
    const float* __restrict__ x, float* __restrict__ out)
{
    extern __shared__ __align__(16) unsigned char smem[];
    int tid = threadIdx.x;
    int warp = tid >> 5;
    int lane = tid & 31;
    int g = lane >> 2, i = lane & 3;

    // fill smem: fragment images + aux
    {
        const uint4* src = (const uint4*)g_fr;
        uint4* dst = (uint4*)smem;
        for (int q = tid; q < FR_TOTAL_U4; q += THREADS) dst[q] = src[q];
        float* sa = (float*)(smem + OFF_AUX);
        for (int q = tid; q < AUX_N; q += THREADS) sa[q] = g_aux[q];
    }
    __syncthreads();

    const uint4* B1f = (const uint4*)(smem + OFF_B1);
    const uint4* B2f = (const uint4*)(smem + OFF_B2);
    const float* sAux = (const float*)(smem + OFF_AUX);
    float* a2buf = (float*)(smem + OFF_A2);

    int rowA = blockIdx.x * ROWS_PER_CTA + warp * 16 + g;   // this lane's rows: rowA, rowA+8
    const float* xr0 = x + (size_t)rowA * 168;
    const float* xr1 = xr0 + 8 * 168;

    // ================= layer 1: mma over K=176, N=88 =================
    float acc[L1_NT][4];
#pragma unroll
    for (int j = 0; j < L1_NT; ++j) {
        acc[j][0] = 0.f; acc[j][1] = 0.f; acc[j][2] = 0.f; acc[j][3] = 0.f;
    }

    for (int t = 0; t < L1_KT; ++t) {
        int c0 = 16 * t + 2 * i;          // low-k pair col
        int c1 = c0 + 8;                  // high-k pair col
        float2 va = *(const float2*)(xr0 + c0);
        float2 vb = *(const float2*)(xr1 + c0);
        float2 vc, vd;
        if (c1 < 167) {                   // t==10 -> c1 >= 168: pad with 0
            vc = *(const float2*)(xr0 + c1);
            vd = *(const float2*)(xr1 + c1);
        } else {
            vc = make_float2(0.f, 0.f); vd = make_float2(0.f, 0.f);
        }
        uint32_t a0h = pack_bf2(va.x, va.y), a1h = pack_bf2(vb.x, vb.y);
        uint32_t a2h = pack_bf2(vc.x, vc.y), a3h = pack_bf2(vd.x, vd.y);
        uint32_t a0l = pack_lo_residual(va.x, va.y, a0h);
        uint32_t a1l = pack_lo_residual(vb.x, vb.y, a1h);
        uint32_t a2l = pack_lo_residual(vc.x, vc.y, a2h);
        uint32_t a3l = pack_lo_residual(vd.x, vd.y, a3h);

#pragma unroll
        for (int j = 0; j < L1_NT; ++j) {
            uint4 bf = B1f[(j * L1_KT + t) * 32 + lane];   // {hi0,hi1,lo0,lo1}
            MMA_BF16(acc[j], a0h, a1h, a2h, a3h, bf.x, bf.y);   // hi*hi
            MMA_BF16(acc[j], a0l, a1l, a2l, a3l, bf.x, bf.y);   // lo*hi
            MMA_BF16(acc[j], a0h, a1h, a2h, a3h, bf.z, bf.w);   // hi*lo
        }
    }

    // ============ epilogue 1: bias + relu (in fragment layout) ============
#pragma unroll
    for (int j = 0; j < L1_NT; ++j) {
        int col0 = 8 * j + 2 * i, col1 = col0 + 1;
        float bb0 = (col0 < 84) ? sAux[X_B1 + col0] : 0.0f;
        float bb1 = (col1 < 84) ? sAux[X_B1 + col1] : 0.0f;
        acc[j][0] = fmaxf(acc[j][0] + bb0, 0.0f);
        acc[j][1] = fmaxf(acc[j][1] + bb1, 0.0f);
        acc[j][2] = fmaxf(acc[j][2] + bb0, 0.0f);
        acc[j][3] = fmaxf(acc[j][3] + bb1, 0.0f);
    }

    // ======= build layer-2 A fragments in registers (no shuffles) =======
    uint32_t a2f_hi[L2_KT][4], a2f_lo[L2_KT][4];
#pragma unroll
    for (int s = 0; s < L2_KT; ++s) {
        int jA = 2 * s, jB = 2 * s + 1;
        float fA0 = acc[jA][0], fA1 = acc[jA][1], fA2 = acc[jA][2], fA3 = acc[jA][3];
        float fB0 = 0.f, fB1 = 0.f, fB2 = 0.f, fB3 = 0.f;
        if (jB < L1_NT) { fB0 = acc[jB][0]; fB1 = acc[jB][1]; fB2 = acc[jB][2]; fB3 = acc[jB][3]; }
        a2f_hi[s][0] = pack_bf2(fA0, fA1);
        a2f_hi[s][1] = pack_bf2(fA2, fA3);
        a2f_hi[s][2] = pack_bf2(fB0, fB1);
        a2f_hi[s][3] = pack_bf2(fB2, fB3);
        a2f_lo[s][0] = pack_lo_residual(fA0, fA1, a2f_hi[s][0]);
        a2f_lo[s][1] = pack_lo_residual(fA2, fA3, a2f_hi[s][1]);
        a2f_lo[s][2] = pack_lo_residual(fB0, fB1, a2f_hi[s][2]);
        a2f_lo[s][3] = pack_lo_residual(fB2, fB3, a2f_hi[s][3]);
    }

    // ================= layer 2: mma over K=96, N=48 =================
    float acc2[L2_NT][4];
#pragma unroll
    for (int j = 0; j < L2_NT; ++j) {
        acc2[j][0] = 0.f; acc2[j][1] = 0.f; acc2[j][2] = 0.f; acc2[j][3] = 0.f;
    }
#pragma unroll
    for (int s = 0; s < L2_KT; ++s) {
#pragma unroll
        for (int j = 0; j < L2_NT; ++j) {
            uint4 bf = B2f[(j * L2_KT + s) * 32 + lane];
            MMA_BF16(acc2[j], a2f_hi[s][0], a2f_hi[s][1], a2f_hi[s][2], a2f_hi[s][3], bf.x, bf.y);
            MMA_BF16(acc2[j], a2f_lo[s][0], a2f_lo[s][1], a2f_lo[s][2], a2f_lo[s][3], bf.x, bf.y);
            MMA_BF16(acc2[j], a2f_hi[s][0], a2f_hi[s][1], a2f_hi[s][2], a2f_hi[s][3], bf.z, bf.w);
        }
    }

    // ====== epilogue 2: bias + relu -> a2buf (stride 43, no conflicts) ======
    {
        int slot0 = warp * 16 + g;       // rows g / g+8 of this warp tile
        int slot1 = slot0 + 8;
#pragma unroll
        for (int j = 0; j < L2_NT; ++j) {
            int col0 = 8 * j + 2 * i, col1 = col0 + 1;
            if (col0 < 42) {
                float bb = sAux[X_B2 + col0];
                a2buf[slot0 * A2_STRIDE + col0] = fmaxf(acc2[j][0] + bb, 0.0f);
                a2buf[slot1 * A2_STRIDE + col0] = fmaxf(acc2[j][2] + bb, 0.0f);
            }
            if (col1 < 42) {
                float bb = sAux[X_B2 + col1];
                a2buf[slot0 * A2_STRIDE + col1] = fmaxf(acc2[j][1] + bb, 0.0f);
                a2buf[slot1 * A2_STRIDE + col1] = fmaxf(acc2[j][3] + bb, 0.0f);
            }
        }
    }

    __syncthreads();

    // ================= scalar tail: layers 3..8, one row per thread =================
    if (tid < ROWS_PER_CTA) {
        float v[42];
#pragma unroll
        for (int k = 0; k < 42; ++k) v[k] = a2buf[tid * A2_STRIDE + k];

        float a3[21]; dense_relu<42, 21>(sAux + X_W3, sAux + X_B3, v,  a3);
        float a4[12]; dense_relu<21, 12>(sAux + X_W4, sAux + X_B4, a3, a4);
        float a5[10]; dense_relu<12, 10>(sAux + X_W5, sAux + X_B5, a4, a5);
        float a6[5];  dense_relu<10, 5>(sAux + X_W6, sAux + X_B6, a5, a6);
        float a7[2];  dense_relu<5, 2>(sAux + X_W7, sAux + X_B7, a6, a7);

        float z = sAux[X_B8];
        z = fmaf(a7[0], sAux[X_W8 + 0], z);
        z = fmaf(a7[1], sAux[X_W8 + 1], z);
        out[blockIdx.x * ROWS_PER_CTA + tid] = 1.0f / (1.0f + expf(-z));
    }
}

// ---------------- launch ----------------
extern "C" void kernel_launch(void* const* d_in, const int* in_sizes, int n_in,
                              void* d_out, int out_size) {
    const float* x  = (const float*)d_in[0];
    const float* W1 = (const float*)d_in[1];
    const float* b1 = (const float*)d_in[2];
    const float* W2 = (const float*)d_in[3];
    const float* b2 = (const float*)d_in[4];
    const float* W3 = (const float*)d_in[5];
    const float* b3 = (const float*)d_in[6];
    const float* W4 = (const float*)d_in[7];
    const float* b4 = (const float*)d_in[8];
    const float* W5 = (const float*)d_in[9];
    const float* b5 = (const float*)d_in[10];
    const float* W6 = (const float*)d_in[11];
    const float* b6 = (const float*)d_in[12];
    const float* W7 = (const float*)d_in[13];
    const float* b7 = (const float*)d_in[14];
    const float* W8 = (const float*)d_in[15];
    const float* b8 = (const float*)d_in[16];
    float* out = (float*)d_out;

    int batch = in_sizes[0] / 168;
    int grid = batch / ROWS_PER_CTA;

    prep_kernel<<<64, 256>>>(W1, b1, W2, b2, W3, b3, W4, b4,
                             W5, b5, W6, b6, W7, b7, W8, b8);

    cudaFuncSetAttribute(mlp_mma_kernel, cudaFuncAttributeMaxDynamicSharedMemorySize, SMEM_TOTAL);
    mlp_mma_kernel<<<grid, THREADS, SMEM_TOTAL>>>(x, out);
}

// round 9
// speedup vs baseline: 3.0468x; 1.0077x over previous
#include <cuda_runtime.h>
#include <cuda_bf16.h>
#include <math.h>
#include <stdint.h>

// ============================================================================
// Fused 8-layer MLP 168->84->42->21->12->10->5->2->1, batch 262144.
// Layers 1-2: warp-level mma.sync bf16, 3-pass hi/lo split, fp32 accum.
// R8: m32 per warp (2 tiles share B-frag loads), vectorized padded tail
// weights, a2buf aliased over dead B1 fragment region (fp32, 2 CTAs/SM).
// (Resubmission of R8 — round failed on broker infra, kernel never ran.)
// ============================================================================

#define THREADS 256
#define ROWS_PER_CTA 256

// mma tile counts
#define L1_NT 11   // n-tiles of 8  (88 >= 84)
#define L1_KT 11   // k-steps of 16 (176 >= 168)
#define L2_NT 6    // 48 >= 42
#define L2_KT 6    // 96 >= 84

// fragment image sizes in uint4 (one uint4 = {hi0, hi1, lo0, lo1})
#define FR1_U4 (L1_NT * L1_KT * 32)    // 3872
#define FR2_U4 (L2_NT * L2_KT * 32)    // 1152
#define FR_TOTAL_U4 (FR1_U4 + FR2_U4)  // 5024

// aux float layout (tail weights padded to 4-float multiples per row)
#define X_B1 0      // 84
#define X_B2 84     // 42
#define X_W3 128    // 21 x 44
#define X_B3 1052   // 21
#define X_W4 1076   // 12 x 24
#define X_B4 1364   // 12
#define X_W5 1376   // 10 x 12
#define X_B5 1496   // 10
#define X_W6 1508   // 5 x 12
#define X_B6 1568   // 5
#define X_W7 1576   // 2 x 8
#define X_B7 1592   // 2
#define X_W8 1596   // 4 (2 real)
#define X_B8 1600   // 1
#define AUX_N 1601

// smem layout (bytes)
#define OFF_B1   0
#define OFF_B2   (OFF_B1 + FR1_U4 * 16)          // 61952
#define OFF_AUX  (OFF_B2 + FR2_U4 * 16)          // 80384
#define SMEM_TOTAL (OFF_AUX + ((AUX_N * 4 + 15) & ~15))  // 86800
// a2buf aliases the (dead) B1 fragment region: 256 rows x stride 44 fp32 = 45056 B
#define OFF_A2   0
#define A2_STRIDE 44

// ---------------- device globals ----------------
__device__ __align__(16) uint4 g_fr[FR_TOTAL_U4];
__device__ __align__(16) float g_aux[AUX_N + 3];

// ---------------- helpers ----------------
__device__ __forceinline__ uint32_t pack_bf2(float f0, float f1) {
    uint32_t r;
    asm("cvt.rn.bf16x2.f32 %0, %1, %2;" : "=r"(r) : "f"(f1), "f"(f0));
    return r;
}
__device__ __forceinline__ uint32_t pack_lo_residual(float f0, float f1, uint32_t hi) {
    float r0 = __uint_as_float(hi << 16);
    float r1 = __uint_as_float(hi & 0xFFFF0000u);
    return pack_bf2(f0 - r0, f1 - r1);
}

#define MMA_BF16(c, a0, a1, a2, a3, b0, b1) \
    asm volatile("mma.sync.aligned.m16n8k16.row.col.f32.bf16.bf16.f32 " \
        "{%0,%1,%2,%3}, {%4,%5,%6,%7}, {%8,%9}, {%0,%1,%2,%3};" \
        : "+f"((c)[0]), "+f"((c)[1]), "+f"((c)[2]), "+f"((c)[3]) \
        : "r"(a0), "r"(a1), "r"(a2), "r"(a3), "r"(b0), "r"(b1))

// Vectorized dense layer: padded row stride INP (mult of 4), OUT real rows,
// out[] padded to OUTP with zeros.
template<int INP, int OUT, int OUTP>
__device__ __forceinline__ void dense_relu_v(const float* __restrict__ sW,
                                             const float* __restrict__ sb,
                                             const float (&in)[INP], float (&out)[OUTP]) {
#pragma unroll
    for (int j = 0; j < OUT; ++j) {
        float a = sb[j];
        const float4* wr = reinterpret_cast<const float4*>(sW + j * INP);
#pragma unroll
        for (int q = 0; q < INP / 4; ++q) {
            float4 w = wr[q];
            a = fmaf(in[4 * q + 0], w.x, a);
            a = fmaf(in[4 * q + 1], w.y, a);
            a = fmaf(in[4 * q + 2], w.z, a);
            a = fmaf(in[4 * q + 3], w.w, a);
        }
        out[j] = fmaxf(a, 0.0f);
    }
#pragma unroll
    for (int j = OUT; j < OUTP; ++j) out[j] = 0.0f;
}

// ---------------- prep kernel ----------------
__global__ void prep_kernel(
    const float* __restrict__ W1, const float* __restrict__ b1,
    const float* __restrict__ W2, const float* __restrict__ b2,
    const float* __restrict__ W3, const float* __restrict__ b3,
    const float* __restrict__ W4, const float* __restrict__ b4,
    const float* __restrict__ W5, const float* __restrict__ b5,
    const float* __restrict__ W6, const float* __restrict__ b6,
    const float* __restrict__ W7, const float* __restrict__ b7,
    const float* __restrict__ W8, const float* __restrict__ b8)
{
    int tid = blockIdx.x * blockDim.x + threadIdx.x;
    int stride = gridDim.x * blockDim.x;

    // layer-1 fragments
    for (int fs = tid; fs < FR1_U4; fs += stride) {
        int j = fs / (L1_KT * 32);
        int rem = fs % (L1_KT * 32);
        int t = rem / 32;
        int lane = rem % 32;
        int g = lane >> 2, i = lane & 3;
        int n = 8 * j + g;
        uint32_t hv[2], lv[2];
#pragma unroll
        for (int r = 0; r < 2; ++r) {
            int k0 = 16 * t + 8 * r + 2 * i;
            float w0 = (n < 84 && k0     < 168) ? W1[n * 168 + k0]     : 0.0f;
            float w1v = (n < 84 && k0 + 1 < 168) ? W1[n * 168 + k0 + 1] : 0.0f;
            __nv_bfloat16 h0 = __float2bfloat16(w0), h1 = __float2bfloat16(w1v);
            float hf0 = __bfloat162float(h0), hf1 = __bfloat162float(h1);
            __nv_bfloat16 l0 = __float2bfloat16(w0 - hf0), l1 = __float2bfloat16(w1v - hf1);
            hv[r] = ((uint32_t)__bfloat16_as_ushort(h1) << 16) | __bfloat16_as_ushort(h0);
            lv[r] = ((uint32_t)__bfloat16_as_ushort(l1) << 16) | __bfloat16_as_ushort(l0);
        }
        g_fr[fs] = make_uint4(hv[0], hv[1], lv[0], lv[1]);
    }
    // layer-2 fragments
    for (int fs = tid; fs < FR2_U4; fs += stride) {
        int j = fs / (L2_KT * 32);
        int rem = fs % (L2_KT * 32);
        int t = rem / 32;
        int lane = rem % 32;
        int g = lane >> 2, i = lane & 3;
        int n = 8 * j + g;
        uint32_t hv[2], lv[2];
#pragma unroll
        for (int r = 0; r < 2; ++r) {
            int k0 = 16 * t + 8 * r + 2 * i;
            float w0 = (n < 42 && k0     < 84) ? W2[n * 84 + k0]     : 0.0f;
            float w1v = (n < 42 && k0 + 1 < 84) ? W2[n * 84 + k0 + 1] : 0.0f;
            __nv_bfloat16 h0 = __float2bfloat16(w0), h1 = __float2bfloat16(w1v);
            float hf0 = __bfloat162float(h0), hf1 = __bfloat162float(h1);
            __nv_bfloat16 l0 = __float2bfloat16(w0 - hf0), l1 = __float2bfloat16(w1v - hf1);
            hv[r] = ((uint32_t)__bfloat16_as_ushort(h1) << 16) | __bfloat16_as_ushort(h0);
            lv[r] = ((uint32_t)__bfloat16_as_ushort(l1) << 16) | __bfloat16_as_ushort(l0);
        }
        g_fr[FR1_U4 + fs] = make_uint4(hv[0], hv[1], lv[0], lv[1]);
    }

    // biases (unpadded)
    for (int i = tid; i < 84; i += stride) g_aux[X_B1 + i] = b1[i];
    for (int i = tid; i < 42; i += stride) g_aux[X_B2 + i] = b2[i];
    for (int i = tid; i < 21; i += stride) g_aux[X_B3 + i] = b3[i];
    for (int i = tid; i < 12; i += stride) g_aux[X_B4 + i] = b4[i];
    for (int i = tid; i < 10; i += stride) g_aux[X_B5 + i] = b5[i];
    for (int i = tid; i < 5;  i += stride) g_aux[X_B6 + i] = b6[i];
    for (int i = tid; i < 2;  i += stride) g_aux[X_B7 + i] = b7[i];
    if (tid == 0) { g_aux[X_B8] = b8[0]; }

    // padded weights
    for (int idx = tid; idx < 21 * 44; idx += stride) {
        int j = idx / 44, k = idx % 44;
        g_aux[X_W3 + idx] = (k < 42) ? W3[j * 42 + k] : 0.0f;
    }
    for (int idx = tid; idx < 12 * 24; idx += stride) {
        int j = idx / 24, k = idx % 24;
        g_aux[X_W4 + idx] = (k < 21) ? W4[j * 21 + k] : 0.0f;
    }
    for (int idx = tid; idx < 10 * 12; idx += stride) {
        g_aux[X_W5 + idx] = W5[idx];   // 10 x 12, exact
    }
    for (int idx = tid; idx < 5 * 12; idx += stride) {
        int j = idx / 12, k = idx % 12;
        g_aux[X_W6 + idx] = (k < 10) ? W6[j * 10 + k] : 0.0f;
    }
    for (int idx = tid; idx < 2 * 8; idx += stride) {
        int j = idx / 8, k = idx % 8;
        g_aux[X_W7 + idx] = (k < 5) ? W7[j * 5 + k] : 0.0f;
    }
    for (int idx = tid; idx < 4; idx += stride) {
        g_aux[X_W8 + idx] = (idx < 2) ? W8[idx] : 0.0f;
    }
}

// ---------------- main kernel ----------------
// grid = batch/256; CTA = 8 warps, each warp two m16 tiles (32 rows).
__global__ void __launch_bounds__(THREADS, 2) mlp_mma_kernel(
    const float* __restrict__ x, float* __restrict__ out)
{
    extern __shared__ __align__(16) unsigned char smem[];
    int tid = threadIdx.x;
    int warp = tid >> 5;
    int lane = tid & 31;
    int g = lane >> 2, i = lane & 3;

    // fill smem: fragment images + aux
    {
        const uint4* src = (const uint4*)g_fr;
        uint4* dst = (uint4*)smem;
        for (int q = tid; q < FR_TOTAL_U4; q += THREADS) dst[q] = src[q];
        float* sa = (float*)(smem + OFF_AUX);
        for (int q = tid; q < AUX_N; q += THREADS) sa[q] = g_aux[q];
    }
    __syncthreads();

    const uint4* B1f = (const uint4*)(smem + OFF_B1);
    const uint4* B2f = (const uint4*)(smem + OFF_B2);
    const float* sAux = (const float*)(smem + OFF_AUX);
    float* a2buf = (float*)(smem + OFF_A2);   // aliases B1 (written after sync)

    int rowA = blockIdx.x * ROWS_PER_CTA + warp * 32 + g;
    const float* xr0 = x + (size_t)rowA * 168;           // tile0 rows g, g+8
    const float* xr1 = xr0 + 8 * 168;
    const float* xr2 = xr0 + 16 * 168;                   // tile1 rows 16+g, 24+g
    const float* xr3 = xr0 + 24 * 168;

    // ================= layer 1: two m16 tiles share B loads =================
    float accA[L1_NT][4], accB[L1_NT][4];
#pragma unroll
    for (int j = 0; j < L1_NT; ++j) {
#pragma unroll
        for (int c = 0; c < 4; ++c) { accA[j][c] = 0.f; accB[j][c] = 0.f; }
    }

    for (int t = 0; t < L1_KT; ++t) {
        int c0 = 16 * t + 2 * i;
        int c1 = c0 + 8;
        float2 vA0 = *(const float2*)(xr0 + c0);
        float2 vA1 = *(const float2*)(xr1 + c0);
        float2 vB0 = *(const float2*)(xr2 + c0);
        float2 vB1 = *(const float2*)(xr3 + c0);
        float2 vA2, vA3, vB2, vB3;
        if (c1 < 167) {
            vA2 = *(const float2*)(xr0 + c1);
            vA3 = *(const float2*)(xr1 + c1);
            vB2 = *(const float2*)(xr2 + c1);
            vB3 = *(const float2*)(xr3 + c1);
        } else {
            vA2 = make_float2(0.f, 0.f); vA3 = make_float2(0.f, 0.f);
            vB2 = make_float2(0.f, 0.f); vB3 = make_float2(0.f, 0.f);
        }
        uint32_t A0h = pack_bf2(vA0.x, vA0.y), A1h = pack_bf2(vA1.x, vA1.y);
        uint32_t A2h = pack_bf2(vA2.x, vA2.y), A3h = pack_bf2(vA3.x, vA3.y);
        uint32_t A0l = pack_lo_residual(vA0.x, vA0.y, A0h);
        uint32_t A1l = pack_lo_residual(vA1.x, vA1.y, A1h);
        uint32_t A2l = pack_lo_residual(vA2.x, vA2.y, A2h);
        uint32_t A3l = pack_lo_residual(vA3.x, vA3.y, A3h);
        uint32_t B0h = pack_bf2(vB0.x, vB0.y), B1h_ = pack_bf2(vB1.x, vB1.y);
        uint32_t B2h = pack_bf2(vB2.x, vB2.y), B3h = pack_bf2(vB3.x, vB3.y);
        uint32_t B0l = pack_lo_residual(vB0.x, vB0.y, B0h);
        uint32_t B1l_ = pack_lo_residual(vB1.x, vB1.y, B1h_);
        uint32_t B2l = pack_lo_residual(vB2.x, vB2.y, B2h);
        uint32_t B3l = pack_lo_residual(vB3.x, vB3.y, B3h);

#pragma unroll
        for (int j = 0; j < L1_NT; ++j) {
            uint4 bf = B1f[(j * L1_KT + t) * 32 + lane];   // {hi0,hi1,lo0,lo1}
            MMA_BF16(accA[j], A0h, A1h, A2h, A3h, bf.x, bf.y);
            MMA_BF16(accA[j], A0l, A1l, A2l, A3l, bf.x, bf.y);
            MMA_BF16(accA[j], A0h, A1h, A2h, A3h, bf.z, bf.w);
            MMA_BF16(accB[j], B0h, B1h_, B2h, B3h, bf.x, bf.y);
            MMA_BF16(accB[j], B0l, B1l_, B2l, B3l, bf.x, bf.y);
            MMA_BF16(accB[j], B0h, B1h_, B2h, B3h, bf.z, bf.w);
        }
    }

    // ============ epilogue 1: bias + relu (both tiles, in regs) ============
#pragma unroll
    for (int j = 0; j < L1_NT; ++j) {
        int col0 = 8 * j + 2 * i, col1 = col0 + 1;
        float bb0 = (col0 < 84) ? sAux[X_B1 + col0] : 0.0f;
        float bb1 = (col1 < 84) ? sAux[X_B1 + col1] : 0.0f;
        accA[j][0] = fmaxf(accA[j][0] + bb0, 0.0f);
        accA[j][1] = fmaxf(accA[j][1] + bb1, 0.0f);
        accA[j][2] = fmaxf(accA[j][2] + bb0, 0.0f);
        accA[j][3] = fmaxf(accA[j][3] + bb1, 0.0f);
        accB[j][0] = fmaxf(accB[j][0] + bb0, 0.0f);
        accB[j][1] = fmaxf(accB[j][1] + bb1, 0.0f);
        accB[j][2] = fmaxf(accB[j][2] + bb0, 0.0f);
        accB[j][3] = fmaxf(accB[j][3] + bb1, 0.0f);
    }

    // ======= layer 2, tile A: repack + mma =======
    float acc2A[L2_NT][4], acc2B[L2_NT][4];
    {
        uint32_t fh[L2_KT][4], fl[L2_KT][4];
#pragma unroll
        for (int s = 0; s < L2_KT; ++s) {
            int jA = 2 * s, jB = 2 * s + 1;
            float f0 = accA[jA][0], f1 = accA[jA][1], f2 = accA[jA][2], f3 = accA[jA][3];
            float h0 = 0.f, h1 = 0.f, h2 = 0.f, h3 = 0.f;
            if (jB < L1_NT) { h0 = accA[jB][0]; h1 = accA[jB][1]; h2 = accA[jB][2]; h3 = accA[jB][3]; }
            fh[s][0] = pack_bf2(f0, f1); fh[s][1] = pack_bf2(f2, f3);
            fh[s][2] = pack_bf2(h0, h1); fh[s][3] = pack_bf2(h2, h3);
            fl[s][0] = pack_lo_residual(f0, f1, fh[s][0]);
            fl[s][1] = pack_lo_residual(f2, f3, fh[s][1]);
            fl[s][2] = pack_lo_residual(h0, h1, fh[s][2]);
            fl[s][3] = pack_lo_residual(h2, h3, fh[s][3]);
        }
#pragma unroll
        for (int j = 0; j < L2_NT; ++j) {
#pragma unroll
            for (int c = 0; c < 4; ++c) acc2A[j][c] = 0.f;
        }
#pragma unroll
        for (int s = 0; s < L2_KT; ++s) {
#pragma unroll
            for (int j = 0; j < L2_NT; ++j) {
                uint4 bf = B2f[(j * L2_KT + s) * 32 + lane];
                MMA_BF16(acc2A[j], fh[s][0], fh[s][1], fh[s][2], fh[s][3], bf.x, bf.y);
                MMA_BF16(acc2A[j], fl[s][0], fl[s][1], fl[s][2], fl[s][3], bf.x, bf.y);
                MMA_BF16(acc2A[j], fh[s][0], fh[s][1], fh[s][2], fh[s][3], bf.z, bf.w);
            }
        }
    }
    // ======= layer 2, tile B: repack + mma =======
    {
        uint32_t fh[L2_KT][4], fl[L2_KT][4];
#pragma unroll
        for (int s = 0; s < L2_KT; ++s) {
            int jA = 2 * s, jB = 2 * s + 1;
            float f0 = accB[jA][0], f1 = accB[jA][1], f2 = accB[jA][2], f3 = accB[jA][3];
            float h0 = 0.f, h1 = 0.f, h2 = 0.f, h3 = 0.f;
            if (jB < L1_NT) { h0 = accB[jB][0]; h1 = accB[jB][1]; h2 = accB[jB][2]; h3 = accB[jB][3]; }
            fh[s][0] = pack_bf2(f0, f1); fh[s][1] = pack_bf2(f2, f3);
            fh[s][2] = pack_bf2(h0, h1); fh[s][3] = pack_bf2(h2, h3);
            fl[s][0] = pack_lo_residual(f0, f1, fh[s][0]);
            fl[s][1] = pack_lo_residual(f2, f3, fh[s][1]);
            fl[s][2] = pack_lo_residual(h0, h1, fh[s][2]);
            fl[s][3] = pack_lo_residual(h2, h3, fh[s][3]);
        }
#pragma unroll
        for (int j = 0; j < L2_NT; ++j) {
#pragma unroll
            for (int c = 0; c < 4; ++c) acc2B[j][c] = 0.f;
        }
#pragma unroll
        for (int s = 0; s < L2_KT; ++s) {
#pragma unroll
            for (int j = 0; j < L2_NT; ++j) {
                uint4 bf = B2f[(j * L2_KT + s) * 32 + lane];
                MMA_BF16(acc2B[j], fh[s][0], fh[s][1], fh[s][2], fh[s][3], bf.x, bf.y);
                MMA_BF16(acc2B[j], fl[s][0], fl[s][1], fl[s][2], fl[s][3], bf.x, bf.y);
                MMA_BF16(acc2B[j], fh[s][0], fh[s][1], fh[s][2], fh[s][3], bf.z, bf.w);
            }
        }
    }

    // all warps done reading B1/B2 fragment images -> safe to alias a2buf
    __syncthreads();

    // ====== epilogue 2: bias + relu -> a2buf (stride 44, float2 stores) ======
    {
        int slotA0 = warp * 32 + g;        // tile A rows
        int slotA1 = slotA0 + 8;
        int slotB0 = slotA0 + 16;          // tile B rows
        int slotB1 = slotA0 + 24;
#pragma unroll
        for (int j = 0; j < L2_NT; ++j) {
            int col0 = 8 * j + 2 * i;
            if (col0 < 42) {
                float b0v = sAux[X_B2 + col0];
                float b1v = (col0 + 1 < 42) ? sAux[X_B2 + col0 + 1] : 0.0f;
                float2 pA0 = make_float2(fmaxf(acc2A[j][0] + b0v, 0.f),
                                         (col0 + 1 < 42) ? fmaxf(acc2A[j][1] + b1v, 0.f) : 0.f);
                float2 pA1 = make_float2(fmaxf(acc2A[j][2] + b0v, 0.f),
                                         (col0 + 1 < 42) ? fmaxf(acc2A[j][3] + b1v, 0.f) : 0.f);
                float2 pB0 = make_float2(fmaxf(acc2B[j][0] + b0v, 0.f),
                                         (col0 + 1 < 42) ? fmaxf(acc2B[j][1] + b1v, 0.f) : 0.f);
                float2 pB1 = make_float2(fmaxf(acc2B[j][2] + b0v, 0.f),
                                         (col0 + 1 < 42) ? fmaxf(acc2B[j][3] + b1v, 0.f) : 0.f);
                *(float2*)(a2buf + slotA0 * A2_STRIDE + col0) = pA0;
                *(float2*)(a2buf + slotA1 * A2_STRIDE + col0) = pA1;
                *(float2*)(a2buf + slotB0 * A2_STRIDE + col0) = pB0;
                *(float2*)(a2buf + slotB1 * A2_STRIDE + col0) = pB1;
            }
        }
    }

    __syncthreads();

    // ================= scalar tail: layers 3..8, one row per thread =================
    {
        float v[44];
        const float4* vr = (const float4*)(a2buf + tid * A2_STRIDE);
#pragma unroll
        for (int q = 0; q < 11; ++q) {
            float4 t4 = vr[q];
            v[4 * q + 0] = t4.x; v[4 * q + 1] = t4.y;
            v[4 * q + 2] = t4.z; v[4 * q + 3] = t4.w;
        }
        v[42] = 0.0f; v[43] = 0.0f;

        float a3[24]; dense_relu_v<44, 21, 24>(sAux + X_W3, sAux + X_B3, v,  a3);
        float a4[12]; dense_relu_v<24, 12, 12>(sAux + X_W4, sAux + X_B4, a3, a4);
        float a5[12]; dense_relu_v<12, 10, 12>(sAux + X_W5, sAux + X_B5, a4, a5);
        float a6[8];  dense_relu_v<12, 5,  8>(sAux + X_W6, sAux + X_B6, a5, a6);
        float a7[2];  dense_relu_v<8,  2,  2>(sAux + X_W7, sAux + X_B7, a6, a7);

        float z = sAux[X_B8];
        z = fmaf(a7[0], sAux[X_W8 + 0], z);
        z = fmaf(a7[1], sAux[X_W8 + 1], z);
        out[blockIdx.x * ROWS_PER_CTA + tid] = 1.0f / (1.0f + expf(-z));
    }
}

// ---------------- launch ----------------
extern "C" void kernel_launch(void* const* d_in, const int* in_sizes, int n_in,
                              void* d_out, int out_size) {
    const float* x  = (const float*)d_in[0];
    const float* W1 = (const float*)d_in[1];
    const float* b1 = (const float*)d_in[2];
    const float* W2 = (const float*)d_in[3];
    const float* b2 = (const float*)d_in[4];
    const float* W3 = (const float*)d_in[5];
    const float* b3 = (const float*)d_in[6];
    const float* W4 = (const float*)d_in[7];
    const float* b4 = (const float*)d_in[8];
    const float* W5 = (const float*)d_in[9];
    const float* b5 = (const float*)d_in[10];
    const float* W6 = (const float*)d_in[11];
    const float* b6 = (const float*)d_in[12];
    const float* W7 = (const float*)d_in[13];
    const float* b7 = (const float*)d_in[14];
    const float* W8 = (const float*)d_in[15];
    const float* b8 = (const float*)d_in[16];
    float* out = (float*)d_out;

    int batch = in_sizes[0] / 168;
    int grid = batch / ROWS_PER_CTA;

    prep_kernel<<<64, 256>>>(W1, b1, W2, b2, W3, b3, W4, b4,
                             W5, b5, W6, b6, W7, b7, W8, b8);

    cudaFuncSetAttribute(mlp_mma_kernel, cudaFuncAttributeMaxDynamicSharedMemorySize, SMEM_TOTAL);
    mlp_mma_kernel<<<grid, THREADS, SMEM_TOTAL>>>(x, out);
}

// round 10
// speedup vs baseline: 3.5635x; 1.1696x over previous
#include <cuda_runtime.h>
#include <cuda_bf16.h>
#include <math.h>
#include <stdint.h>

// ============================================================================
// Fused 8-layer MLP 168->84->42->21->12->10->5->2->1, batch 262144.
// Layers 1-2: warp-level mma.sync bf16, 3-pass hi/lo split, fp32 accum.
// R10: m32 per warp kept, but register-liveness restructured to kill spills:
//  - repack folded into s-loop (8 transient regs, not 48 persistent)
//  - layer-2 tile A fully retired (smem) before tile B starts
//  - vectorized padded tail weights; a2buf aliases dead B1 fragment region.
// ============================================================================

#define THREADS 256
#define ROWS_PER_CTA 256

// mma tile counts
#define L1_NT 11   // n-tiles of 8  (88 >= 84)
#define L1_KT 11   // k-steps of 16 (176 >= 168)
#define L2_NT 6    // 48 >= 42
#define L2_KT 6    // 96 >= 84

// fragment image sizes in uint4 (one uint4 = {hi0, hi1, lo0, lo1})
#define FR1_U4 (L1_NT * L1_KT * 32)    // 3872
#define FR2_U4 (L2_NT * L2_KT * 32)    // 1152
#define FR_TOTAL_U4 (FR1_U4 + FR2_U4)  // 5024

// aux float layout (tail weights padded to 4-float multiples per row)
#define X_B1 0      // 84
#define X_B2 84     // 42
#define X_W3 128    // 21 x 44
#define X_B3 1052   // 21
#define X_W4 1076   // 12 x 24
#define X_B4 1364   // 12
#define X_W5 1376   // 10 x 12
#define X_B5 1496   // 10
#define X_W6 1508   // 5 x 12
#define X_B6 1568   // 5
#define X_W7 1576   // 2 x 8
#define X_B7 1592   // 2
#define X_W8 1596   // 4 (2 real)
#define X_B8 1600   // 1
#define AUX_N 1601

// smem layout (bytes)
#define OFF_B1   0
#define OFF_B2   (OFF_B1 + FR1_U4 * 16)          // 61952
#define OFF_AUX  (OFF_B2 + FR2_U4 * 16)          // 80384
#define SMEM_TOTAL (OFF_AUX + ((AUX_N * 4 + 15) & ~15))  // 86800
// a2buf aliases the (dead) B1 fragment region: 256 rows x stride 44 fp32 = 45056 B
#define OFF_A2   0
#define A2_STRIDE 44

// ---------------- device globals ----------------
__device__ __align__(16) uint4 g_fr[FR_TOTAL_U4];
__device__ __align__(16) float g_aux[AUX_N + 3];

// ---------------- helpers ----------------
__device__ __forceinline__ uint32_t pack_bf2(float f0, float f1) {
    uint32_t r;
    asm("cvt.rn.bf16x2.f32 %0, %1, %2;" : "=r"(r) : "f"(f1), "f"(f0));
    return r;
}
__device__ __forceinline__ uint32_t pack_lo_residual(float f0, float f1, uint32_t hi) {
    float r0 = __uint_as_float(hi << 16);
    float r1 = __uint_as_float(hi & 0xFFFF0000u);
    return pack_bf2(f0 - r0, f1 - r1);
}

#define MMA_BF16(c, a0, a1, a2, a3, b0, b1) \
    asm volatile("mma.sync.aligned.m16n8k16.row.col.f32.bf16.bf16.f32 " \
        "{%0,%1,%2,%3}, {%4,%5,%6,%7}, {%8,%9}, {%0,%1,%2,%3};" \
        : "+f"((c)[0]), "+f"((c)[1]), "+f"((c)[2]), "+f"((c)[3]) \
        : "r"(a0), "r"(a1), "r"(a2), "r"(a3), "r"(b0), "r"(b1))

// Vectorized dense layer: padded row stride INP (mult of 4), OUT real rows,
// out[] padded to OUTP with zeros.
template<int INP, int OUT, int OUTP>
__device__ __forceinline__ void dense_relu_v(const float* __restrict__ sW,
                                             const float* __restrict__ sb,
                                             const float (&in)[INP], float (&out)[OUTP]) {
#pragma unroll
    for (int j = 0; j < OUT; ++j) {
        float a = sb[j];
        const float4* wr = reinterpret_cast<const float4*>(sW + j * INP);
#pragma unroll
        for (int q = 0; q < INP / 4; ++q) {
            float4 w = wr[q];
            a = fmaf(in[4 * q + 0], w.x, a);
            a = fmaf(in[4 * q + 1], w.y, a);
            a = fmaf(in[4 * q + 2], w.z, a);
            a = fmaf(in[4 * q + 3], w.w, a);
        }
        out[j] = fmaxf(a, 0.0f);
    }
#pragma unroll
    for (int j = OUT; j < OUTP; ++j) out[j] = 0.0f;
}

// ---------------- prep kernel ----------------
__global__ void prep_kernel(
    const float* __restrict__ W1, const float* __restrict__ b1,
    const float* __restrict__ W2, const float* __restrict__ b2,
    const float* __restrict__ W3, const float* __restrict__ b3,
    const float* __restrict__ W4, const float* __restrict__ b4,
    const float* __restrict__ W5, const float* __restrict__ b5,
    const float* __restrict__ W6, const float* __restrict__ b6,
    const float* __restrict__ W7, const float* __restrict__ b7,
    const float* __restrict__ W8, const float* __restrict__ b8)
{
    int tid = blockIdx.x * blockDim.x + threadIdx.x;
    int stride = gridDim.x * blockDim.x;

    // layer-1 fragments
    for (int fs = tid; fs < FR1_U4; fs += stride) {
        int j = fs / (L1_KT * 32);
        int rem = fs % (L1_KT * 32);
        int t = rem / 32;
        int lane = rem % 32;
        int g = lane >> 2, i = lane & 3;
        int n = 8 * j + g;
        uint32_t hv[2], lv[2];
#pragma unroll
        for (int r = 0; r < 2; ++r) {
            int k0 = 16 * t + 8 * r + 2 * i;
            float w0 = (n < 84 && k0     < 168) ? W1[n * 168 + k0]     : 0.0f;
            float w1v = (n < 84 && k0 + 1 < 168) ? W1[n * 168 + k0 + 1] : 0.0f;
            __nv_bfloat16 h0 = __float2bfloat16(w0), h1 = __float2bfloat16(w1v);
            float hf0 = __bfloat162float(h0), hf1 = __bfloat162float(h1);
            __nv_bfloat16 l0 = __float2bfloat16(w0 - hf0), l1 = __float2bfloat16(w1v - hf1);
            hv[r] = ((uint32_t)__bfloat16_as_ushort(h1) << 16) | __bfloat16_as_ushort(h0);
            lv[r] = ((uint32_t)__bfloat16_as_ushort(l1) << 16) | __bfloat16_as_ushort(l0);
        }
        g_fr[fs] = make_uint4(hv[0], hv[1], lv[0], lv[1]);
    }
    // layer-2 fragments
    for (int fs = tid; fs < FR2_U4; fs += stride) {
        int j = fs / (L2_KT * 32);
        int rem = fs % (L2_KT * 32);
        int t = rem / 32;
        int lane = rem % 32;
        int g = lane >> 2, i = lane & 3;
        int n = 8 * j + g;
        uint32_t hv[2], lv[2];
#pragma unroll
        for (int r = 0; r < 2; ++r) {
            int k0 = 16 * t + 8 * r + 2 * i;
            float w0 = (n < 42 && k0     < 84) ? W2[n * 84 + k0]     : 0.0f;
            float w1v = (n < 42 && k0 + 1 < 84) ? W2[n * 84 + k0 + 1] : 0.0f;
            __nv_bfloat16 h0 = __float2bfloat16(w0), h1 = __float2bfloat16(w1v);
            float hf0 = __bfloat162float(h0), hf1 = __bfloat162float(h1);
            __nv_bfloat16 l0 = __float2bfloat16(w0 - hf0), l1 = __float2bfloat16(w1v - hf1);
            hv[r] = ((uint32_t)__bfloat16_as_ushort(h1) << 16) | __bfloat16_as_ushort(h0);
            lv[r] = ((uint32_t)__bfloat16_as_ushort(l1) << 16) | __bfloat16_as_ushort(l0);
        }
        g_fr[FR1_U4 + fs] = make_uint4(hv[0], hv[1], lv[0], lv[1]);
    }

    // biases (unpadded)
    for (int i = tid; i < 84; i += stride) g_aux[X_B1 + i] = b1[i];
    for (int i = tid; i < 42; i += stride) g_aux[X_B2 + i] = b2[i];
    for (int i = tid; i < 21; i += stride) g_aux[X_B3 + i] = b3[i];
    for (int i = tid; i < 12; i += stride) g_aux[X_B4 + i] = b4[i];
    for (int i = tid; i < 10; i += stride) g_aux[X_B5 + i] = b5[i];
    for (int i = tid; i < 5;  i += stride) g_aux[X_B6 + i] = b6[i];
    for (int i = tid; i < 2;  i += stride) g_aux[X_B7 + i] = b7[i];
    if (tid == 0) { g_aux[X_B8] = b8[0]; }

    // padded weights
    for (int idx = tid; idx < 21 * 44; idx += stride) {
        int j = idx / 44, k = idx % 44;
        g_aux[X_W3 + idx] = (k < 42) ? W3[j * 42 + k] : 0.0f;
    }
    for (int idx = tid; idx < 12 * 24; idx += stride) {
        int j = idx / 24, k = idx % 24;
        g_aux[X_W4 + idx] = (k < 21) ? W4[j * 21 + k] : 0.0f;
    }
    for (int idx = tid; idx < 10 * 12; idx += stride) {
        g_aux[X_W5 + idx] = W5[idx];   // 10 x 12, exact
    }
    for (int idx = tid; idx < 5 * 12; idx += stride) {
        int j = idx / 12, k = idx % 12;
        g_aux[X_W6 + idx] = (k < 10) ? W6[j * 10 + k] : 0.0f;
    }
    for (int idx = tid; idx < 2 * 8; idx += stride) {
        int j = idx / 8, k = idx % 8;
        g_aux[X_W7 + idx] = (k < 5) ? W7[j * 5 + k] : 0.0f;
    }
    for (int idx = tid; idx < 4; idx += stride) {
        g_aux[X_W8 + idx] = (idx < 2) ? W8[idx] : 0.0f;
    }
}

// Layer-2 for one m16 tile: on-the-fly repack from acc (layer-1 result,
// bias+relu already applied), MMA vs B2 frags, epilogue to a2buf.
// acc is consumed; transient register cost: 8 (fh/fl) + 24 (acc2) + frag.
__device__ __forceinline__ void layer2_tile(
    const float (&acc)[L1_NT][4], const uint4* __restrict__ B2f,
    const float* __restrict__ sAux, float* __restrict__ a2buf,
    int lane, int slot0)
{
    int i = lane & 3;
    float acc2[L2_NT][4];
#pragma unroll
    for (int j = 0; j < L2_NT; ++j) {
#pragma unroll
        for (int c = 0; c < 4; ++c) acc2[j][c] = 0.f;
    }
#pragma unroll
    for (int s = 0; s < L2_KT; ++s) {
        int jA = 2 * s, jB = 2 * s + 1;
        float f0 = acc[jA][0], f1 = acc[jA][1], f2 = acc[jA][2], f3 = acc[jA][3];
        float h0 = 0.f, h1 = 0.f, h2 = 0.f, h3 = 0.f;
        if (jB < L1_NT) { h0 = acc[jB][0]; h1 = acc[jB][1]; h2 = acc[jB][2]; h3 = acc[jB][3]; }
        uint32_t fh0 = pack_bf2(f0, f1), fh1 = pack_bf2(f2, f3);
        uint32_t fh2 = pack_bf2(h0, h1), fh3 = pack_bf2(h2, h3);
        uint32_t fl0 = pack_lo_residual(f0, f1, fh0);
        uint32_t fl1 = pack_lo_residual(f2, f3, fh1);
        uint32_t fl2 = pack_lo_residual(h0, h1, fh2);
        uint32_t fl3 = pack_lo_residual(h2, h3, fh3);
#pragma unroll
        for (int j = 0; j < L2_NT; ++j) {
            uint4 bf = B2f[(j * L2_KT + s) * 32 + lane];
            MMA_BF16(acc2[j], fh0, fh1, fh2, fh3, bf.x, bf.y);
            MMA_BF16(acc2[j], fl0, fl1, fl2, fl3, bf.x, bf.y);
            MMA_BF16(acc2[j], fh0, fh1, fh2, fh3, bf.z, bf.w);
        }
    }
    // epilogue: bias + relu -> a2buf (stride 44, float2 stores, conflict-free)
    int slot1 = slot0 + 8;
#pragma unroll
    for (int j = 0; j < L2_NT; ++j) {
        int col0 = 8 * j + 2 * i;
        if (col0 < 42) {
            float b0v = sAux[X_B2 + col0];
            float b1v = (col0 + 1 < 42) ? sAux[X_B2 + col0 + 1] : 0.0f;
            float2 p0 = make_float2(fmaxf(acc2[j][0] + b0v, 0.f),
                                    (col0 + 1 < 42) ? fmaxf(acc2[j][1] + b1v, 0.f) : 0.f);
            float2 p1 = make_float2(fmaxf(acc2[j][2] + b0v, 0.f),
                                    (col0 + 1 < 42) ? fmaxf(acc2[j][3] + b1v, 0.f) : 0.f);
            *(float2*)(a2buf + slot0 * A2_STRIDE + col0) = p0;
            *(float2*)(a2buf + slot1 * A2_STRIDE + col0) = p1;
        }
    }
}

// ---------------- main kernel ----------------
// grid = batch/256; CTA = 8 warps, each warp two m16 tiles (32 rows).
__global__ void __launch_bounds__(THREADS, 2) mlp_mma_kernel(
    const float* __restrict__ x, float* __restrict__ out)
{
    extern __shared__ __align__(16) unsigned char smem[];
    int tid = threadIdx.x;
    int warp = tid >> 5;
    int lane = tid & 31;
    int g = lane >> 2, i = lane & 3;

    // fill smem: fragment images + aux
    {
        const uint4* src = (const uint4*)g_fr;
        uint4* dst = (uint4*)smem;
        for (int q = tid; q < FR_TOTAL_U4; q += THREADS) dst[q] = src[q];
        float* sa = (float*)(smem + OFF_AUX);
        for (int q = tid; q < AUX_N; q += THREADS) sa[q] = g_aux[q];
    }
    __syncthreads();

    const uint4* B1f = (const uint4*)(smem + OFF_B1);
    const uint4* B2f = (const uint4*)(smem + OFF_B2);
    const float* sAux = (const float*)(smem + OFF_AUX);
    float* a2buf = (float*)(smem + OFF_A2);   // aliases B1 (written after sync)

    int rowA = blockIdx.x * ROWS_PER_CTA + warp * 32 + g;
    const float* xr0 = x + (size_t)rowA * 168;           // tile0 rows g, g+8
    const float* xr1 = xr0 + 8 * 168;
    const float* xr2 = xr0 + 16 * 168;                   // tile1 rows 16+g, 24+g
    const float* xr3 = xr0 + 24 * 168;

    // ================= layer 1: two m16 tiles share B loads =================
    float accA[L1_NT][4], accB[L1_NT][4];
#pragma unroll
    for (int j = 0; j < L1_NT; ++j) {
#pragma unroll
        for (int c = 0; c < 4; ++c) { accA[j][c] = 0.f; accB[j][c] = 0.f; }
    }

    for (int t = 0; t < L1_KT; ++t) {
        int c0 = 16 * t + 2 * i;
        int c1 = c0 + 8;
        float2 vA0 = *(const float2*)(xr0 + c0);
        float2 vA1 = *(const float2*)(xr1 + c0);
        float2 vB0 = *(const float2*)(xr2 + c0);
        float2 vB1 = *(const float2*)(xr3 + c0);
        float2 vA2, vA3, vB2, vB3;
        if (c1 < 167) {
            vA2 = *(const float2*)(xr0 + c1);
            vA3 = *(const float2*)(xr1 + c1);
            vB2 = *(const float2*)(xr2 + c1);
            vB3 = *(const float2*)(xr3 + c1);
        } else {
            vA2 = make_float2(0.f, 0.f); vA3 = make_float2(0.f, 0.f);
            vB2 = make_float2(0.f, 0.f); vB3 = make_float2(0.f, 0.f);
        }
        uint32_t A0h = pack_bf2(vA0.x, vA0.y), A1h = pack_bf2(vA1.x, vA1.y);
        uint32_t A2h = pack_bf2(vA2.x, vA2.y), A3h = pack_bf2(vA3.x, vA3.y);
        uint32_t A0l = pack_lo_residual(vA0.x, vA0.y, A0h);
        uint32_t A1l = pack_lo_residual(vA1.x, vA1.y, A1h);
        uint32_t A2l = pack_lo_residual(vA2.x, vA2.y, A2h);
        uint32_t A3l = pack_lo_residual(vA3.x, vA3.y, A3h);
        uint32_t B0h = pack_bf2(vB0.x, vB0.y), B1h_ = pack_bf2(vB1.x, vB1.y);
        uint32_t B2h = pack_bf2(vB2.x, vB2.y), B3h = pack_bf2(vB3.x, vB3.y);
        uint32_t B0l = pack_lo_residual(vB0.x, vB0.y, B0h);
        uint32_t B1l_ = pack_lo_residual(vB1.x, vB1.y, B1h_);
        uint32_t B2l = pack_lo_residual(vB2.x, vB2.y, B2h);
        uint32_t B3l = pack_lo_residual(vB3.x, vB3.y, B3h);

#pragma unroll
        for (int j = 0; j < L1_NT; ++j) {
            uint4 bf = B1f[(j * L1_KT + t) * 32 + lane];   // {hi0,hi1,lo0,lo1}
            MMA_BF16(accA[j], A0h, A1h, A2h, A3h, bf.x, bf.y);
            MMA_BF16(accA[j], A0l, A1l, A2l, A3l, bf.x, bf.y);
            MMA_BF16(accA[j], A0h, A1h, A2h, A3h, bf.z, bf.w);
            MMA_BF16(accB[j], B0h, B1h_, B2h, B3h, bf.x, bf.y);
            MMA_BF16(accB[j], B0l, B1l_, B2l, B3l, bf.x, bf.y);
            MMA_BF16(accB[j], B0h, B1h_, B2h, B3h, bf.z, bf.w);
        }
    }

    // ============ epilogue 1: bias + relu (both tiles, in regs) ============
#pragma unroll
    for (int j = 0; j < L1_NT; ++j) {
        int col0 = 8 * j + 2 * i, col1 = col0 + 1;
        float bb0 = (col0 < 84) ? sAux[X_B1 + col0] : 0.0f;
        float bb1 = (col1 < 84) ? sAux[X_B1 + col1] : 0.0f;
        accA[j][0] = fmaxf(accA[j][0] + bb0, 0.0f);
        accA[j][1] = fmaxf(accA[j][1] + bb1, 0.0f);
        accA[j][2] = fmaxf(accA[j][2] + bb0, 0.0f);
        accA[j][3] = fmaxf(accA[j][3] + bb1, 0.0f);
        accB[j][0] = fmaxf(accB[j][0] + bb0, 0.0f);
        accB[j][1] = fmaxf(accB[j][1] + bb1, 0.0f);
        accB[j][2] = fmaxf(accB[j][2] + bb0, 0.0f);
        accB[j][3] = fmaxf(accB[j][3] + bb1, 0.0f);
    }

    // All warps are past their last B1 read -> a2buf (aliasing B1) is writable.
    __syncthreads();

    // ======= layer 2 + epilogue 2: tile A fully retired, then tile B =======
    // (sequencing shares acc2/fh/fl registers between the two tiles)
    layer2_tile(accA, B2f, sAux, a2buf, lane, warp * 32 + g);
    layer2_tile(accB, B2f, sAux, a2buf, lane, warp * 32 + g + 16);

    __syncthreads();

    // ================= scalar tail: layers 3..8, one row per thread =================
    {
        float v[44];
        const float4* vr = (const float4*)(a2buf + tid * A2_STRIDE);
#pragma unroll
        for (int q = 0; q < 11; ++q) {
            float4 t4 = vr[q];
            v[4 * q + 0] = t4.x; v[4 * q + 1] = t4.y;
            v[4 * q + 2] = t4.z; v[4 * q + 3] = t4.w;
        }
        v[42] = 0.0f; v[43] = 0.0f;

        float a3[24]; dense_relu_v<44, 21, 24>(sAux + X_W3, sAux + X_B3, v,  a3);
        float a4[12]; dense_relu_v<24, 12, 12>(sAux + X_W4, sAux + X_B4, a3, a4);
        float a5[12]; dense_relu_v<12, 10, 12>(sAux + X_W5, sAux + X_B5, a4, a5);
        float a6[8];  dense_relu_v<12, 5,  8>(sAux + X_W6, sAux + X_B6, a5, a6);
        float a7[2];  dense_relu_v<8,  2,  2>(sAux + X_W7, sAux + X_B7, a6, a7);

        float z = sAux[X_B8];
        z = fmaf(a7[0], sAux[X_W8 + 0], z);
        z = fmaf(a7[1], sAux[X_W8 + 1], z);
        out[blockIdx.x * ROWS_PER_CTA + tid] = 1.0f / (1.0f + expf(-z));
    }
}

// ---------------- launch ----------------
extern "C" void kernel_launch(void* const* d_in, const int* in_sizes, int n_in,
                              void* d_out, int out_size) {
    const float* x  = (const float*)d_in[0];
    const float* W1 = (const float*)d_in[1];
    const float* b1 = (const float*)d_in[2];
    const float* W2 = (const float*)d_in[3];
    const float* b2 = (const float*)d_in[4];
    const float* W3 = (const float*)d_in[5];
    const float* b3 = (const float*)d_in[6];
    const float* W4 = (const float*)d_in[7];
    const float* b4 = (const float*)d_in[8];
    const float* W5 = (const float*)d_in[9];
    const float* b5 = (const float*)d_in[10];
    const float* W6 = (const float*)d_in[11];
    const float* b6 = (const float*)d_in[12];
    const float* W7 = (const float*)d_in[13];
    const float* b7 = (const float*)d_in[14];
    const float* W8 = (const float*)d_in[15];
    const float* b8 = (const float*)d_in[16];
    float* out = (float*)d_out;

    int batch = in_sizes[0] / 168;
    int grid = batch / ROWS_PER_CTA;

    prep_kernel<<<64, 256>>>(W1, b1, W2, b2, W3, b3, W4, b4,
                             W5, b5, W6, b6, W7, b7, W8, b8);

    cudaFuncSetAttribute(mlp_mma_kernel, cudaFuncAttributeMaxDynamicSharedMemorySize, SMEM_TOTAL);
    mlp_mma_kernel<<<grid, THREADS, SMEM_TOTAL>>>(x, out);
}

// round 11
// speedup vs baseline: 4.0531x; 1.1374x over previous
#include <cuda_runtime.h>
#include <cuda_bf16.h>
#include <math.h>
#include <stdint.h>

// ============================================================================
// Fused 8-layer MLP 168->84->42->21->12->10->5->2->1, batch 262144.
// ALL dense layers on warp-level mma.sync bf16 (3-pass hi/lo split, fp32
// accum), chained in fragment layout (C-frag of layer L == A-frag of L+1,
// ntiles paired). No scalar tail, no inter-warp activation smem.
// ============================================================================

#define THREADS 256
#define ROWS_PER_CTA 256

// per-layer mma tile counts: NT = n-tiles of 8, KT = k-steps of 16
#define NT1 11
#define KT1 11
#define NT2 6
#define KT2 6
#define NT3 3
#define KT3 3
#define NT4 2
#define KT4 2
#define NT5 2
#define KT5 1
#define NT6 1
#define KT6 1
#define NT7 1
#define KT7 1

// fragment image sizes in uint4 ({hi0,hi1,lo0,lo1} per lane per (j,t))
#define FR1 (NT1 * KT1 * 32)   // 3872
#define FR2 (NT2 * KT2 * 32)   // 1152
#define FR3 (NT3 * KT3 * 32)   // 288
#define FR4 (NT4 * KT4 * 32)   // 128
#define FR5 (NT5 * KT5 * 32)   // 64
#define FR6 (NT6 * KT6 * 32)   // 32
#define FR7 (NT7 * KT7 * 32)   // 32
#define U4_B1 0
#define U4_B2 (U4_B1 + FR1)    // 3872
#define U4_B3 (U4_B2 + FR2)    // 5024
#define U4_B4 (U4_B3 + FR3)    // 5312
#define U4_B5 (U4_B4 + FR4)    // 5440
#define U4_B6 (U4_B5 + FR5)    // 5504
#define U4_B7 (U4_B6 + FR6)    // 5536
#define FR_TOTAL (U4_B7 + FR7) // 5568

// aux float layout (biases + final layer)
#define X_B1 0     // 84
#define X_B2 84    // 42
#define X_B3 126   // 21
#define X_B4 147   // 12
#define X_B5 159   // 10
#define X_B6 169   // 5
#define X_B7 174   // 2
#define X_W8 176   // 2
#define X_B8 178   // 1
#define AUX_N 179

// smem layout (bytes)
#define OFF_FR  0
#define OFF_AUX (FR_TOTAL * 16)                       // 89088
#define SMEM_TOTAL (OFF_AUX + ((AUX_N * 4 + 15) & ~15))  // 89808

// ---------------- device globals ----------------
__device__ __align__(16) uint4 g_fr[FR_TOTAL];
__device__ __align__(16) float g_aux[AUX_N + 1];

// ---------------- helpers ----------------
__device__ __forceinline__ uint32_t pack_bf2(float f0, float f1) {
    uint32_t r;
    asm("cvt.rn.bf16x2.f32 %0, %1, %2;" : "=r"(r) : "f"(f1), "f"(f0));
    return r;
}
__device__ __forceinline__ uint32_t pack_lo_residual(float f0, float f1, uint32_t hi) {
    float r0 = __uint_as_float(hi << 16);
    float r1 = __uint_as_float(hi & 0xFFFF0000u);
    return pack_bf2(f0 - r0, f1 - r1);
}

#define MMA_BF16(c, a0, a1, a2, a3, b0, b1) \
    asm volatile("mma.sync.aligned.m16n8k16.row.col.f32.bf16.bf16.f32 " \
        "{%0,%1,%2,%3}, {%4,%5,%6,%7}, {%8,%9}, {%0,%1,%2,%3};" \
        : "+f"((c)[0]), "+f"((c)[1]), "+f"((c)[2]), "+f"((c)[3]) \
        : "r"(a0), "r"(a1), "r"(a2), "r"(a3), "r"(b0), "r"(b1))

// ---------------- prep kernel ----------------
// B fragment for m16n8k16 .row.col (g=lane>>2, i=lane&3), B[k][n] = W[n][k]:
//  reg r: { W[n][16t+8r+2i], W[n][16t+8r+2i+1] }, n = 8j+g.
__device__ void build_frags(const float* __restrict__ W, int out_dim, int in_dim,
                            int NT, int KT, uint4* __restrict__ dst,
                            int tid, int stride)
{
    int total = NT * KT * 32;
    for (int fs = tid; fs < total; fs += stride) {
        int j = fs / (KT * 32);
        int t = (fs / 32) % KT;
        int lane = fs % 32;
        int g = lane >> 2, i = lane & 3;
        int n = 8 * j + g;
        uint32_t hv[2], lv[2];
#pragma unroll
        for (int r = 0; r < 2; ++r) {
            int k0 = 16 * t + 8 * r + 2 * i;
            float w0 = (n < out_dim && k0     < in_dim) ? W[n * in_dim + k0]     : 0.0f;
            float w1 = (n < out_dim && k0 + 1 < in_dim) ? W[n * in_dim + k0 + 1] : 0.0f;
            __nv_bfloat16 h0 = __float2bfloat16(w0), h1 = __float2bfloat16(w1);
            float hf0 = __bfloat162float(h0), hf1 = __bfloat162float(h1);
            __nv_bfloat16 l0 = __float2bfloat16(w0 - hf0), l1 = __float2bfloat16(w1 - hf1);
            hv[r] = ((uint32_t)__bfloat16_as_ushort(h1) << 16) | __bfloat16_as_ushort(h0);
            lv[r] = ((uint32_t)__bfloat16_as_ushort(l1) << 16) | __bfloat16_as_ushort(l0);
        }
        dst[fs] = make_uint4(hv[0], hv[1], lv[0], lv[1]);
    }
}

__global__ void prep_kernel(
    const float* __restrict__ W1, const float* __restrict__ b1,
    const float* __restrict__ W2, const float* __restrict__ b2,
    const float* __restrict__ W3, const float* __restrict__ b3,
    const float* __restrict__ W4, const float* __restrict__ b4,
    const float* __restrict__ W5, const float* __restrict__ b5,
    const float* __restrict__ W6, const float* __restrict__ b6,
    const float* __restrict__ W7, const float* __restrict__ b7,
    const float* __restrict__ W8, const float* __restrict__ b8)
{
    int tid = blockIdx.x * blockDim.x + threadIdx.x;
    int stride = gridDim.x * blockDim.x;

    build_frags(W1, 84, 168, NT1, KT1, g_fr + U4_B1, tid, stride);
    build_frags(W2, 42, 84,  NT2, KT2, g_fr + U4_B2, tid, stride);
    build_frags(W3, 21, 42,  NT3, KT3, g_fr + U4_B3, tid, stride);
    build_frags(W4, 12, 21,  NT4, KT4, g_fr + U4_B4, tid, stride);
    build_frags(W5, 10, 12,  NT5, KT5, g_fr + U4_B5, tid, stride);
    build_frags(W6, 5,  10,  NT6, KT6, g_fr + U4_B6, tid, stride);
    build_frags(W7, 2,  5,   NT7, KT7, g_fr + U4_B7, tid, stride);

    for (int i = tid; i < 84; i += stride) g_aux[X_B1 + i] = b1[i];
    for (int i = tid; i < 42; i += stride) g_aux[X_B2 + i] = b2[i];
    for (int i = tid; i < 21; i += stride) g_aux[X_B3 + i] = b3[i];
    for (int i = tid; i < 12; i += stride) g_aux[X_B4 + i] = b4[i];
    for (int i = tid; i < 10; i += stride) g_aux[X_B5 + i] = b5[i];
    for (int i = tid; i < 5;  i += stride) g_aux[X_B6 + i] = b6[i];
    for (int i = tid; i < 2;  i += stride) g_aux[X_B7 + i] = b7[i];
    for (int i = tid; i < 2;  i += stride) g_aux[X_W8 + i] = W8[i];
    if (tid == 0) g_aux[X_B8] = b8[0];
}

// ---------------- generic fragment-chained dense layer ----------------
// accIn: previous layer's C frags (bias+relu applied, padded cols zero).
// A k-step s is built from accIn ntile pair (2s, 2s+1).
// Output: bias + relu with column guard (realN).
template<int NT_IN, int KT, int NT_OUT>
__device__ __forceinline__ void frag_layer(
    const float (&accIn)[NT_IN][4], float (&accOut)[NT_OUT][4],
    const uint4* __restrict__ Bf, const float* __restrict__ bias,
    int realN, int lane)
{
    int i = lane & 3;
#pragma unroll
    for (int j = 0; j < NT_OUT; ++j) {
#pragma unroll
        for (int c = 0; c < 4; ++c) accOut[j][c] = 0.f;
    }
#pragma unroll
    for (int s = 0; s < KT; ++s) {
        int jA = 2 * s, jB = 2 * s + 1;
        float f0 = accIn[jA][0], f1 = accIn[jA][1], f2 = accIn[jA][2], f3 = accIn[jA][3];
        float h0 = 0.f, h1 = 0.f, h2 = 0.f, h3 = 0.f;
        if (jB < NT_IN) { h0 = accIn[jB][0]; h1 = accIn[jB][1]; h2 = accIn[jB][2]; h3 = accIn[jB][3]; }
        uint32_t fh0 = pack_bf2(f0, f1), fh1 = pack_bf2(f2, f3);
        uint32_t fh2 = pack_bf2(h0, h1), fh3 = pack_bf2(h2, h3);
        uint32_t fl0 = pack_lo_residual(f0, f1, fh0);
        uint32_t fl1 = pack_lo_residual(f2, f3, fh1);
        uint32_t fl2 = pack_lo_residual(h0, h1, fh2);
        uint32_t fl3 = pack_lo_residual(h2, h3, fh3);
#pragma unroll
        for (int j = 0; j < NT_OUT; ++j) {
            uint4 bf = Bf[(j * KT + s) * 32 + lane];
            MMA_BF16(accOut[j], fh0, fh1, fh2, fh3, bf.x, bf.y);
            MMA_BF16(accOut[j], fl0, fl1, fl2, fl3, bf.x, bf.y);
            MMA_BF16(accOut[j], fh0, fh1, fh2, fh3, bf.z, bf.w);
        }
    }
    // epilogue: bias + relu (padded cols have acc==0 and skip bias -> stay 0)
#pragma unroll
    for (int j = 0; j < NT_OUT; ++j) {
        int col0 = 8 * j + 2 * i, col1 = col0 + 1;
        float bb0 = (col0 < realN) ? bias[col0] : 0.0f;
        float bb1 = (col1 < realN) ? bias[col1] : 0.0f;
        accOut[j][0] = fmaxf(accOut[j][0] + bb0, 0.0f);
        accOut[j][1] = fmaxf(accOut[j][1] + bb1, 0.0f);
        accOut[j][2] = fmaxf(accOut[j][2] + bb0, 0.0f);
        accOut[j][3] = fmaxf(accOut[j][3] + bb1, 0.0f);
    }
}

// layers 2..8 + sigmoid + store for one m16 tile (rows rowBase..rowBase+15)
__device__ __forceinline__ void tail_layers(
    const float (&acc1)[NT1][4],
    const uint4* __restrict__ sFr, const float* __restrict__ sAux,
    float* __restrict__ out, int rowBase, int lane)
{
    int g = lane >> 2, i = lane & 3;
    float acc2[NT2][4];
    frag_layer<NT1, KT2, NT2>(acc1, acc2, sFr + U4_B2, sAux + X_B2, 42, lane);
    float acc3[NT3][4];
    frag_layer<NT2, KT3, NT3>(acc2, acc3, sFr + U4_B3, sAux + X_B3, 21, lane);
    float acc4[NT4][4];
    frag_layer<NT3, KT4, NT4>(acc3, acc4, sFr + U4_B4, sAux + X_B4, 12, lane);
    float acc5[NT5][4];
    frag_layer<NT4, KT5, NT5>(acc4, acc5, sFr + U4_B5, sAux + X_B5, 10, lane);
    float acc6[NT6][4];
    frag_layer<NT5, KT6, NT6>(acc5, acc6, sFr + U4_B6, sAux + X_B6, 5, lane);
    float acc7[NT7][4];
    frag_layer<NT6, KT7, NT7>(acc6, acc7, sFr + U4_B7, sAux + X_B7, 2, lane);

    // layer 8: out = sigmoid(w8 . a7 + b8); lanes i==0 hold cols 0,1
    if (i == 0) {
        float w0 = sAux[X_W8], w1 = sAux[X_W8 + 1], bb = sAux[X_B8];
        float z0 = fmaf(acc7[0][1], w1, fmaf(acc7[0][0], w0, bb));   // row g
        float z1 = fmaf(acc7[0][3], w1, fmaf(acc7[0][2], w0, bb));   // row g+8
        out[rowBase + g]     = 1.0f / (1.0f + expf(-z0));
        out[rowBase + 8 + g] = 1.0f / (1.0f + expf(-z1));
    }
}

// ---------------- main kernel ----------------
// grid = batch/256; CTA = 8 warps, each warp two m16 tiles (32 rows).
__global__ void __launch_bounds__(THREADS, 2) mlp_mma_kernel(
    const float* __restrict__ x, float* __restrict__ out)
{
    extern __shared__ __align__(16) unsigned char smem[];
    int tid = threadIdx.x;
    int warp = tid >> 5;
    int lane = tid & 31;
    int g = lane >> 2, i = lane & 3;

    // fill smem: fragment images + aux
    {
        const uint4* src = (const uint4*)g_fr;
        uint4* dst = (uint4*)(smem + OFF_FR);
        for (int q = tid; q < FR_TOTAL; q += THREADS) dst[q] = src[q];
        float* sa = (float*)(smem + OFF_AUX);
        for (int q = tid; q < AUX_N; q += THREADS) sa[q] = g_aux[q];
    }
    __syncthreads();

    const uint4* sFr = (const uint4*)(smem + OFF_FR);
    const uint4* B1f = sFr + U4_B1;
    const float* sAux = (const float*)(smem + OFF_AUX);

    int rowBase = blockIdx.x * ROWS_PER_CTA + warp * 32;
    const float* xr0 = x + (size_t)(rowBase + g) * 168;  // tile A rows g, g+8
    const float* xr1 = xr0 + 8 * 168;
    const float* xr2 = xr0 + 16 * 168;                   // tile B rows 16+g, 24+g
    const float* xr3 = xr0 + 24 * 168;

    // ================= layer 1: two m16 tiles share B loads =================
    float accA[NT1][4], accB[NT1][4];
#pragma unroll
    for (int j = 0; j < NT1; ++j) {
#pragma unroll
        for (int c = 0; c < 4; ++c) { accA[j][c] = 0.f; accB[j][c] = 0.f; }
    }

    for (int t = 0; t < KT1; ++t) {
        int c0 = 16 * t + 2 * i;
        int c1 = c0 + 8;
        float2 vA0 = *(const float2*)(xr0 + c0);
        float2 vA1 = *(const float2*)(xr1 + c0);
        float2 vB0 = *(const float2*)(xr2 + c0);
        float2 vB1 = *(const float2*)(xr3 + c0);
        float2 vA2, vA3, vB2, vB3;
        if (c1 < 167) {   // t==10 -> c1 >= 168: zero-pad
            vA2 = *(const float2*)(xr0 + c1);
            vA3 = *(const float2*)(xr1 + c1);
            vB2 = *(const float2*)(xr2 + c1);
            vB3 = *(const float2*)(xr3 + c1);
        } else {
            vA2 = make_float2(0.f, 0.f); vA3 = make_float2(0.f, 0.f);
            vB2 = make_float2(0.f, 0.f); vB3 = make_float2(0.f, 0.f);
        }
        uint32_t A0h = pack_bf2(vA0.x, vA0.y), A1h = pack_bf2(vA1.x, vA1.y);
        uint32_t A2h = pack_bf2(vA2.x, vA2.y), A3h = pack_bf2(vA3.x, vA3.y);
        uint32_t A0l = pack_lo_residual(vA0.x, vA0.y, A0h);
        uint32_t A1l = pack_lo_residual(vA1.x, vA1.y, A1h);
        uint32_t A2l = pack_lo_residual(vA2.x, vA2.y, A2h);
        uint32_t A3l = pack_lo_residual(vA3.x, vA3.y, A3h);
        uint32_t B0h = pack_bf2(vB0.x, vB0.y), B1h_ = pack_bf2(vB1.x, vB1.y);
        uint32_t B2h = pack_bf2(vB2.x, vB2.y), B3h = pack_bf2(vB3.x, vB3.y);
        uint32_t B0l = pack_lo_residual(vB0.x, vB0.y, B0h);
        uint32_t B1l_ = pack_lo_residual(vB1.x, vB1.y, B1h_);
        uint32_t B2l = pack_lo_residual(vB2.x, vB2.y, B2h);
        uint32_t B3l = pack_lo_residual(vB3.x, vB3.y, B3h);

#pragma unroll
        for (int j = 0; j < NT1; ++j) {
            uint4 bf = B1f[(j * KT1 + t) * 32 + lane];   // {hi0,hi1,lo0,lo1}
            MMA_BF16(accA[j], A0h, A1h, A2h, A3h, bf.x, bf.y);
            MMA_BF16(accA[j], A0l, A1l, A2l, A3l, bf.x, bf.y);
            MMA_BF16(accA[j], A0h, A1h, A2h, A3h, bf.z, bf.w);
            MMA_BF16(accB[j], B0h, B1h_, B2h, B3h, bf.x, bf.y);
            MMA_BF16(accB[j], B0l, B1l_, B2l, B3l, bf.x, bf.y);
            MMA_BF16(accB[j], B0h, B1h_, B2h, B3h, bf.z, bf.w);
        }
    }

    // ============ epilogue 1: bias + relu (both tiles, in regs) ============
#pragma unroll
    for (int j = 0; j < NT1; ++j) {
        int col0 = 8 * j + 2 * i, col1 = col0 + 1;
        float bb0 = (col0 < 84) ? sAux[X_B1 + col0] : 0.0f;
        float bb1 = (col1 < 84) ? sAux[X_B1 + col1] : 0.0f;
        accA[j][0] = fmaxf(accA[j][0] + bb0, 0.0f);
        accA[j][1] = fmaxf(accA[j][1] + bb1, 0.0f);
        accA[j][2] = fmaxf(accA[j][2] + bb0, 0.0f);
        accA[j][3] = fmaxf(accA[j][3] + bb1, 0.0f);
        accB[j][0] = fmaxf(accB[j][0] + bb0, 0.0f);
        accB[j][1] = fmaxf(accB[j][1] + bb1, 0.0f);
        accB[j][2] = fmaxf(accB[j][2] + bb0, 0.0f);
        accB[j][3] = fmaxf(accB[j][3] + bb1, 0.0f);
    }

    // ======= layers 2..8 fully in fragment layout, tile A then tile B =======
    tail_layers(accA, sFr, sAux, out, rowBase, lane);
    tail_layers(accB, sFr, sAux, out, rowBase + 16, lane);
}

// ---------------- launch ----------------
extern "C" void kernel_launch(void* const* d_in, const int* in_sizes, int n_in,
                              void* d_out, int out_size) {
    const float* x  = (const float*)d_in[0];
    const float* W1 = (const float*)d_in[1];
    const float* b1 = (const float*)d_in[2];
    const float* W2 = (const float*)d_in[3];
    const float* b2 = (const float*)d_in[4];
    const float* W3 = (const float*)d_in[5];
    const float* b3 = (const float*)d_in[6];
    const float* W4 = (const float*)d_in[7];
    const float* b4 = (const float*)d_in[8];
    const float* W5 = (const float*)d_in[9];
    const float* b5 = (const float*)d_in[10];
    const float* W6 = (const float*)d_in[11];
    const float* b6 = (const float*)d_in[12];
    const float* W7 = (const float*)d_in[13];
    const float* b7 = (const float*)d_in[14];
    const float* W8 = (const float*)d_in[15];
    const float* b8 = (const float*)d_in[16];
    float* out = (float*)d_out;

    int batch = in_sizes[0] / 168;
    int grid = batch / ROWS_PER_CTA;

    prep_kernel<<<64, 256>>>(W1, b1, W2, b2, W3, b3, W4, b4,
                             W5, b5, W6, b6, W7, b7, W8, b8);

    cudaFuncSetAttribute(mlp_mma_kernel, cudaFuncAttributeMaxDynamicSharedMemorySize, SMEM_TOTAL);
    mlp_mma_kernel<<<grid, THREADS, SMEM_TOTAL>>>(x, out);
}

// round 12
// speedup vs baseline: 4.2645x; 1.0522x over previous
#include <cuda_runtime.h>
#include <cuda_bf16.h>
#include <math.h>
#include <stdint.h>

// ============================================================================
// Fused 8-layer MLP 168->84->42->21->12->10->5->2->1, batch 262144.
// ALL dense layers on warp-level mma.sync bf16 (3-pass hi/lo split, fp32
// accum), chained in fragment layout. R12: layers 3-8 processed dual-tile
// (shared B-fragment loads, 2x MMA ILP in the dependency-bound small layers).
// ============================================================================

#define THREADS 256
#define ROWS_PER_CTA 256

// per-layer mma tile counts: NT = n-tiles of 8, KT = k-steps of 16
#define NT1 11
#define KT1 11
#define NT2 6
#define KT2 6
#define NT3 3
#define KT3 3
#define NT4 2
#define KT4 2
#define NT5 2
#define KT5 1
#define NT6 1
#define KT6 1
#define NT7 1
#define KT7 1

// fragment image sizes in uint4 ({hi0,hi1,lo0,lo1} per lane per (j,t))
#define FR1 (NT1 * KT1 * 32)   // 3872
#define FR2 (NT2 * KT2 * 32)   // 1152
#define FR3 (NT3 * KT3 * 32)   // 288
#define FR4 (NT4 * KT4 * 32)   // 128
#define FR5 (NT5 * KT5 * 32)   // 64
#define FR6 (NT6 * KT6 * 32)   // 32
#define FR7 (NT7 * KT7 * 32)   // 32
#define U4_B1 0
#define U4_B2 (U4_B1 + FR1)    // 3872
#define U4_B3 (U4_B2 + FR2)    // 5024
#define U4_B4 (U4_B3 + FR3)    // 5312
#define U4_B5 (U4_B4 + FR4)    // 5440
#define U4_B6 (U4_B5 + FR5)    // 5504
#define U4_B7 (U4_B6 + FR6)    // 5536
#define FR_TOTAL (U4_B7 + FR7) // 5568

// aux float layout (biases + final layer)
#define X_B1 0     // 84
#define X_B2 84    // 42
#define X_B3 126   // 21
#define X_B4 147   // 12
#define X_B5 159   // 10
#define X_B6 169   // 5
#define X_B7 174   // 2
#define X_W8 176   // 2
#define X_B8 178   // 1
#define AUX_N 179

// smem layout (bytes)
#define OFF_FR  0
#define OFF_AUX (FR_TOTAL * 16)                       // 89088
#define SMEM_TOTAL (OFF_AUX + ((AUX_N * 4 + 15) & ~15))  // 89808

// ---------------- device globals ----------------
__device__ __align__(16) uint4 g_fr[FR_TOTAL];
__device__ __align__(16) float g_aux[AUX_N + 1];

// ---------------- helpers ----------------
__device__ __forceinline__ uint32_t pack_bf2(float f0, float f1) {
    uint32_t r;
    asm("cvt.rn.bf16x2.f32 %0, %1, %2;" : "=r"(r) : "f"(f1), "f"(f0));
    return r;
}
__device__ __forceinline__ uint32_t pack_lo_residual(float f0, float f1, uint32_t hi) {
    float r0 = __uint_as_float(hi << 16);
    float r1 = __uint_as_float(hi & 0xFFFF0000u);
    return pack_bf2(f0 - r0, f1 - r1);
}

#define MMA_BF16(c, a0, a1, a2, a3, b0, b1) \
    asm volatile("mma.sync.aligned.m16n8k16.row.col.f32.bf16.bf16.f32 " \
        "{%0,%1,%2,%3}, {%4,%5,%6,%7}, {%8,%9}, {%0,%1,%2,%3};" \
        : "+f"((c)[0]), "+f"((c)[1]), "+f"((c)[2]), "+f"((c)[3]) \
        : "r"(a0), "r"(a1), "r"(a2), "r"(a3), "r"(b0), "r"(b1))

// ---------------- prep kernel ----------------
// B fragment for m16n8k16 .row.col (g=lane>>2, i=lane&3), B[k][n] = W[n][k]:
//  reg r: { W[n][16t+8r+2i], W[n][16t+8r+2i+1] }, n = 8j+g.
__device__ void build_frags(const float* __restrict__ W, int out_dim, int in_dim,
                            int NT, int KT, uint4* __restrict__ dst,
                            int tid, int stride)
{
    int total = NT * KT * 32;
    for (int fs = tid; fs < total; fs += stride) {
        int j = fs / (KT * 32);
        int t = (fs / 32) % KT;
        int lane = fs % 32;
        int g = lane >> 2, i = lane & 3;
        int n = 8 * j + g;
        uint32_t hv[2], lv[2];
#pragma unroll
        for (int r = 0; r < 2; ++r) {
            int k0 = 16 * t + 8 * r + 2 * i;
            float w0 = (n < out_dim && k0     < in_dim) ? W[n * in_dim + k0]     : 0.0f;
            float w1 = (n < out_dim && k0 + 1 < in_dim) ? W[n * in_dim + k0 + 1] : 0.0f;
            __nv_bfloat16 h0 = __float2bfloat16(w0), h1 = __float2bfloat16(w1);
            float hf0 = __bfloat162float(h0), hf1 = __bfloat162float(h1);
            __nv_bfloat16 l0 = __float2bfloat16(w0 - hf0), l1 = __float2bfloat16(w1 - hf1);
            hv[r] = ((uint32_t)__bfloat16_as_ushort(h1) << 16) | __bfloat16_as_ushort(h0);
            lv[r] = ((uint32_t)__bfloat16_as_ushort(l1) << 16) | __bfloat16_as_ushort(l0);
        }
        dst[fs] = make_uint4(hv[0], hv[1], lv[0], lv[1]);
    }
}

__global__ void prep_kernel(
    const float* __restrict__ W1, const float* __restrict__ b1,
    const float* __restrict__ W2, const float* __restrict__ b2,
    const float* __restrict__ W3, const float* __restrict__ b3,
    const float* __restrict__ W4, const float* __restrict__ b4,
    const float* __restrict__ W5, const float* __restrict__ b5,
    const float* __restrict__ W6, const float* __restrict__ b6,
    const float* __restrict__ W7, const float* __restrict__ b7,
    const float* __restrict__ W8, const float* __restrict__ b8)
{
    int tid = blockIdx.x * blockDim.x + threadIdx.x;
    int stride = gridDim.x * blockDim.x;

    build_frags(W1, 84, 168, NT1, KT1, g_fr + U4_B1, tid, stride);
    build_frags(W2, 42, 84,  NT2, KT2, g_fr + U4_B2, tid, stride);
    build_frags(W3, 21, 42,  NT3, KT3, g_fr + U4_B3, tid, stride);
    build_frags(W4, 12, 21,  NT4, KT4, g_fr + U4_B4, tid, stride);
    build_frags(W5, 10, 12,  NT5, KT5, g_fr + U4_B5, tid, stride);
    build_frags(W6, 5,  10,  NT6, KT6, g_fr + U4_B6, tid, stride);
    build_frags(W7, 2,  5,   NT7, KT7, g_fr + U4_B7, tid, stride);

    for (int i = tid; i < 84; i += stride) g_aux[X_B1 + i] = b1[i];
    for (int i = tid; i < 42; i += stride) g_aux[X_B2 + i] = b2[i];
    for (int i = tid; i < 21; i += stride) g_aux[X_B3 + i] = b3[i];
    for (int i = tid; i < 12; i += stride) g_aux[X_B4 + i] = b4[i];
    for (int i = tid; i < 10; i += stride) g_aux[X_B5 + i] = b5[i];
    for (int i = tid; i < 5;  i += stride) g_aux[X_B6 + i] = b6[i];
    for (int i = tid; i < 2;  i += stride) g_aux[X_B7 + i] = b7[i];
    for (int i = tid; i < 2;  i += stride) g_aux[X_W8 + i] = W8[i];
    if (tid == 0) g_aux[X_B8] = b8[0];
}

// ---------------- single-tile fragment-chained dense layer (layer 2) --------
template<int NT_IN, int KT, int NT_OUT>
__device__ __forceinline__ void frag_layer(
    const float (&accIn)[NT_IN][4], float (&accOut)[NT_OUT][4],
    const uint4* __restrict__ Bf, const float* __restrict__ bias,
    int realN, int lane)
{
    int i = lane & 3;
#pragma unroll
    for (int j = 0; j < NT_OUT; ++j) {
#pragma unroll
        for (int c = 0; c < 4; ++c) accOut[j][c] = 0.f;
    }
#pragma unroll
    for (int s = 0; s < KT; ++s) {
        int jA = 2 * s, jB = 2 * s + 1;
        float f0 = accIn[jA][0], f1 = accIn[jA][1], f2 = accIn[jA][2], f3 = accIn[jA][3];
        float h0 = 0.f, h1 = 0.f, h2 = 0.f, h3 = 0.f;
        if (jB < NT_IN) { h0 = accIn[jB][0]; h1 = accIn[jB][1]; h2 = accIn[jB][2]; h3 = accIn[jB][3]; }
        uint32_t fh0 = pack_bf2(f0, f1), fh1 = pack_bf2(f2, f3);
        uint32_t fh2 = pack_bf2(h0, h1), fh3 = pack_bf2(h2, h3);
        uint32_t fl0 = pack_lo_residual(f0, f1, fh0);
        uint32_t fl1 = pack_lo_residual(f2, f3, fh1);
        uint32_t fl2 = pack_lo_residual(h0, h1, fh2);
        uint32_t fl3 = pack_lo_residual(h2, h3, fh3);
#pragma unroll
        for (int j = 0; j < NT_OUT; ++j) {
            uint4 bf = Bf[(j * KT + s) * 32 + lane];
            MMA_BF16(accOut[j], fh0, fh1, fh2, fh3, bf.x, bf.y);
            MMA_BF16(accOut[j], fl0, fl1, fl2, fl3, bf.x, bf.y);
            MMA_BF16(accOut[j], fh0, fh1, fh2, fh3, bf.z, bf.w);
        }
    }
#pragma unroll
    for (int j = 0; j < NT_OUT; ++j) {
        int col0 = 8 * j + 2 * i, col1 = col0 + 1;
        float bb0 = (col0 < realN) ? bias[col0] : 0.0f;
        float bb1 = (col1 < realN) ? bias[col1] : 0.0f;
        accOut[j][0] = fmaxf(accOut[j][0] + bb0, 0.0f);
        accOut[j][1] = fmaxf(accOut[j][1] + bb1, 0.0f);
        accOut[j][2] = fmaxf(accOut[j][2] + bb0, 0.0f);
        accOut[j][3] = fmaxf(accOut[j][3] + bb1, 0.0f);
    }
}

// ---------------- dual-tile layer (layers 3..7): one B-frag load feeds
// 6 MMAs (3 per tile, independent accumulator chains) ----------------
template<int NT_IN, int KT, int NT_OUT>
__device__ __forceinline__ void frag_layer_dual(
    const float (&inA)[NT_IN][4], const float (&inB)[NT_IN][4],
    float (&outA)[NT_OUT][4], float (&outB)[NT_OUT][4],
    const uint4* __restrict__ Bf, const float* __restrict__ bias,
    int realN, int lane)
{
    int i = lane & 3;
#pragma unroll
    for (int j = 0; j < NT_OUT; ++j) {
#pragma unroll
        for (int c = 0; c < 4; ++c) { outA[j][c] = 0.f; outB[j][c] = 0.f; }
    }
#pragma unroll
    for (int s = 0; s < KT; ++s) {
        int jA = 2 * s, jB = 2 * s + 1;
        // repack tile A
        float fA0 = inA[jA][0], fA1 = inA[jA][1], fA2 = inA[jA][2], fA3 = inA[jA][3];
        float hA0 = 0.f, hA1 = 0.f, hA2 = 0.f, hA3 = 0.f;
        if (jB < NT_IN) { hA0 = inA[jB][0]; hA1 = inA[jB][1]; hA2 = inA[jB][2]; hA3 = inA[jB][3]; }
        uint32_t ah0 = pack_bf2(fA0, fA1), ah1 = pack_bf2(fA2, fA3);
        uint32_t ah2 = pack_bf2(hA0, hA1), ah3 = pack_bf2(hA2, hA3);
        uint32_t al0 = pack_lo_residual(fA0, fA1, ah0);
        uint32_t al1 = pack_lo_residual(fA2, fA3, ah1);
        uint32_t al2 = pack_lo_residual(hA0, hA1, ah2);
        uint32_t al3 = pack_lo_residual(hA2, hA3, ah3);
        // repack tile B
        float fB0 = inB[jA][0], fB1 = inB[jA][1], fB2 = inB[jA][2], fB3 = inB[jA][3];
        float hB0 = 0.f, hB1 = 0.f, hB2 = 0.f, hB3 = 0.f;
        if (jB < NT_IN) { hB0 = inB[jB][0]; hB1 = inB[jB][1]; hB2 = inB[jB][2]; hB3 = inB[jB][3]; }
        uint32_t bh0 = pack_bf2(fB0, fB1), bh1 = pack_bf2(fB2, fB3);
        uint32_t bh2 = pack_bf2(hB0, hB1), bh3 = pack_bf2(hB2, hB3);
        uint32_t bl0 = pack_lo_residual(fB0, fB1, bh0);
        uint32_t bl1 = pack_lo_residual(fB2, fB3, bh1);
        uint32_t bl2 = pack_lo_residual(hB0, hB1, bh2);
        uint32_t bl3 = pack_lo_residual(hB2, hB3, bh3);
#pragma unroll
        for (int j = 0; j < NT_OUT; ++j) {
            uint4 bf = Bf[(j * KT + s) * 32 + lane];   // one load, 6 MMAs
            MMA_BF16(outA[j], ah0, ah1, ah2, ah3, bf.x, bf.y);
            MMA_BF16(outB[j], bh0, bh1, bh2, bh3, bf.x, bf.y);
            MMA_BF16(outA[j], al0, al1, al2, al3, bf.x, bf.y);
            MMA_BF16(outB[j], bl0, bl1, bl2, bl3, bf.x, bf.y);
            MMA_BF16(outA[j], ah0, ah1, ah2, ah3, bf.z, bf.w);
            MMA_BF16(outB[j], bh0, bh1, bh2, bh3, bf.z, bf.w);
        }
    }
#pragma unroll
    for (int j = 0; j < NT_OUT; ++j) {
        int col0 = 8 * j + 2 * i, col1 = col0 + 1;
        float bb0 = (col0 < realN) ? bias[col0] : 0.0f;
        float bb1 = (col1 < realN) ? bias[col1] : 0.0f;
        outA[j][0] = fmaxf(outA[j][0] + bb0, 0.0f);
        outA[j][1] = fmaxf(outA[j][1] + bb1, 0.0f);
        outA[j][2] = fmaxf(outA[j][2] + bb0, 0.0f);
        outA[j][3] = fmaxf(outA[j][3] + bb1, 0.0f);
        outB[j][0] = fmaxf(outB[j][0] + bb0, 0.0f);
        outB[j][1] = fmaxf(outB[j][1] + bb1, 0.0f);
        outB[j][2] = fmaxf(outB[j][2] + bb0, 0.0f);
        outB[j][3] = fmaxf(outB[j][3] + bb1, 0.0f);
    }
}

// ---------------- main kernel ----------------
// grid = batch/256; CTA = 8 warps, each warp two m16 tiles (32 rows).
__global__ void __launch_bounds__(THREADS, 2) mlp_mma_kernel(
    const float* __restrict__ x, float* __restrict__ out)
{
    extern __shared__ __align__(16) unsigned char smem[];
    int tid = threadIdx.x;
    int warp = tid >> 5;
    int lane = tid & 31;
    int g = lane >> 2, i = lane & 3;

    // fill smem: fragment images + aux
    {
        const uint4* src = (const uint4*)g_fr;
        uint4* dst = (uint4*)(smem + OFF_FR);
        for (int q = tid; q < FR_TOTAL; q += THREADS) dst[q] = src[q];
        float* sa = (float*)(smem + OFF_AUX);
        for (int q = tid; q < AUX_N; q += THREADS) sa[q] = g_aux[q];
    }
    __syncthreads();

    const uint4* sFr = (const uint4*)(smem + OFF_FR);
    const uint4* B1f = sFr + U4_B1;
    const float* sAux = (const float*)(smem + OFF_AUX);

    int rowBase = blockIdx.x * ROWS_PER_CTA + warp * 32;
    const float* xr0 = x + (size_t)(rowBase + g) * 168;  // tile A rows g, g+8
    const float* xr1 = xr0 + 8 * 168;
    const float* xr2 = xr0 + 16 * 168;                   // tile B rows 16+g, 24+g
    const float* xr3 = xr0 + 24 * 168;

    // ================= layer 1: two m16 tiles share B loads =================
    float accA[NT1][4], accB[NT1][4];
#pragma unroll
    for (int j = 0; j < NT1; ++j) {
#pragma unroll
        for (int c = 0; c < 4; ++c) { accA[j][c] = 0.f; accB[j][c] = 0.f; }
    }

    for (int t = 0; t < KT1; ++t) {
        int c0 = 16 * t + 2 * i;
        int c1 = c0 + 8;
        float2 vA0 = *(const float2*)(xr0 + c0);
        float2 vA1 = *(const float2*)(xr1 + c0);
        float2 vB0 = *(const float2*)(xr2 + c0);
        float2 vB1 = *(const float2*)(xr3 + c0);
        float2 vA2, vA3, vB2, vB3;
        if (c1 < 167) {   // t==10 -> c1 >= 168: zero-pad
            vA2 = *(const float2*)(xr0 + c1);
            vA3 = *(const float2*)(xr1 + c1);
            vB2 = *(const float2*)(xr2 + c1);
            vB3 = *(const float2*)(xr3 + c1);
        } else {
            vA2 = make_float2(0.f, 0.f); vA3 = make_float2(0.f, 0.f);
            vB2 = make_float2(0.f, 0.f); vB3 = make_float2(0.f, 0.f);
        }
        uint32_t A0h = pack_bf2(vA0.x, vA0.y), A1h = pack_bf2(vA1.x, vA1.y);
        uint32_t A2h = pack_bf2(vA2.x, vA2.y), A3h = pack_bf2(vA3.x, vA3.y);
        uint32_t A0l = pack_lo_residual(vA0.x, vA0.y, A0h);
        uint32_t A1l = pack_lo_residual(vA1.x, vA1.y, A1h);
        uint32_t A2l = pack_lo_residual(vA2.x, vA2.y, A2h);
        uint32_t A3l = pack_lo_residual(vA3.x, vA3.y, A3h);
        uint32_t B0h = pack_bf2(vB0.x, vB0.y), B1h_ = pack_bf2(vB1.x, vB1.y);
        uint32_t B2h = pack_bf2(vB2.x, vB2.y), B3h = pack_bf2(vB3.x, vB3.y);
        uint32_t B0l = pack_lo_residual(vB0.x, vB0.y, B0h);
        uint32_t B1l_ = pack_lo_residual(vB1.x, vB1.y, B1h_);
        uint32_t B2l = pack_lo_residual(vB2.x, vB2.y, B2h);
        uint32_t B3l = pack_lo_residual(vB3.x, vB3.y, B3h);

#pragma unroll
        for (int j = 0; j < NT1; ++j) {
            uint4 bf = B1f[(j * KT1 + t) * 32 + lane];   // {hi0,hi1,lo0,lo1}
            MMA_BF16(accA[j], A0h, A1h, A2h, A3h, bf.x, bf.y);
            MMA_BF16(accB[j], B0h, B1h_, B2h, B3h, bf.x, bf.y);
            MMA_BF16(accA[j], A0l, A1l, A2l, A3l, bf.x, bf.y);
            MMA_BF16(accB[j], B0l, B1l_, B2l, B3l, bf.x, bf.y);
            MMA_BF16(accA[j], A0h, A1h, A2h, A3h, bf.z, bf.w);
            MMA_BF16(accB[j], B0h, B1h_, B2h, B3h, bf.z, bf.w);
        }
    }

    // ============ epilogue 1: bias + relu (both tiles, in regs) ============
#pragma unroll
    for (int j = 0; j < NT1; ++j) {
        int col0 = 8 * j + 2 * i, col1 = col0 + 1;
        float bb0 = (col0 < 84) ? sAux[X_B1 + col0] : 0.0f;
        float bb1 = (col1 < 84) ? sAux[X_B1 + col1] : 0.0f;
        accA[j][0] = fmaxf(accA[j][0] + bb0, 0.0f);
        accA[j][1] = fmaxf(accA[j][1] + bb1, 0.0f);
        accA[j][2] = fmaxf(accA[j][2] + bb0, 0.0f);
        accA[j][3] = fmaxf(accA[j][3] + bb1, 0.0f);
        accB[j][0] = fmaxf(accB[j][0] + bb0, 0.0f);
        accB[j][1] = fmaxf(accB[j][1] + bb1, 0.0f);
        accB[j][2] = fmaxf(accB[j][2] + bb0, 0.0f);
        accB[j][3] = fmaxf(accB[j][3] + bb1, 0.0f);
    }

    // ======= layer 2: per tile (register ceiling), tile A then tile B =======
    float acc2A[NT2][4];
    frag_layer<NT1, KT2, NT2>(accA, acc2A, sFr + U4_B2, sAux + X_B2, 42, lane);
    float acc2B[NT2][4];
    frag_layer<NT1, KT2, NT2>(accB, acc2B, sFr + U4_B2, sAux + X_B2, 42, lane);

    // ======= layers 3..7: dual-tile, shared frag loads, 2x ILP =======
    float acc3A[NT3][4], acc3B[NT3][4];
    frag_layer_dual<NT2, KT3, NT3>(acc2A, acc2B, acc3A, acc3B, sFr + U4_B3, sAux + X_B3, 21, lane);
    float acc4A[NT4][4], acc4B[NT4][4];
    frag_layer_dual<NT3, KT4, NT4>(acc3A, acc3B, acc4A, acc4B, sFr + U4_B4, sAux + X_B4, 12, lane);
    float acc5A[NT5][4], acc5B[NT5][4];
    frag_layer_dual<NT4, KT5, NT5>(acc4A, acc4B, acc5A, acc5B, sFr + U4_B5, sAux + X_B5, 10, lane);
    float acc6A[NT6][4], acc6B[NT6][4];
    frag_layer_dual<NT5, KT6, NT6>(acc5A, acc5B, acc6A, acc6B, sFr + U4_B6, sAux + X_B6, 5, lane);
    float acc7A[NT7][4], acc7B[NT7][4];
    frag_layer_dual<NT6, KT7, NT7>(acc6A, acc6B, acc7A, acc7B, sFr + U4_B7, sAux + X_B7, 2, lane);

    // ======= layer 8 + sigmoid, both tiles; lanes i==0 hold cols 0,1 =======
    if (i == 0) {
        float w0 = sAux[X_W8], w1 = sAux[X_W8 + 1], bb = sAux[X_B8];
        float zA0 = fmaf(acc7A[0][1], w1, fmaf(acc7A[0][0], w0, bb));   // row g
        float zA1 = fmaf(acc7A[0][3], w1, fmaf(acc7A[0][2], w0, bb));   // row g+8
        float zB0 = fmaf(acc7B[0][1], w1, fmaf(acc7B[0][0], w0, bb));   // row 16+g
        float zB1 = fmaf(acc7B[0][3], w1, fmaf(acc7B[0][2], w0, bb));   // row 24+g
        out[rowBase + g]      = 1.0f / (1.0f + expf(-zA0));
        out[rowBase + 8 + g]  = 1.0f / (1.0f + expf(-zA1));
        out[rowBase + 16 + g] = 1.0f / (1.0f + expf(-zB0));
        out[rowBase + 24 + g] = 1.0f / (1.0f + expf(-zB1));
    }
}

// ---------------- launch ----------------
extern "C" void kernel_launch(void* const* d_in, const int* in_sizes, int n_in,
                              void* d_out, int out_size) {
    const float* x  = (const float*)d_in[0];
    const float* W1 = (const float*)d_in[1];
    const float* b1 = (const float*)d_in[2];
    const float* W2 = (const float*)d_in[3];
    const float* b2 = (const float*)d_in[4];
    const float* W3 = (const float*)d_in[5];
    const float* b3 = (const float*)d_in[6];
    const float* W4 = (const float*)d_in[7];
    const float* b4 = (const float*)d_in[8];
    const float* W5 = (const float*)d_in[9];
    const float* b5 = (const float*)d_in[10];
    const float* W6 = (const float*)d_in[11];
    const float* b6 = (const float*)d_in[12];
    const float* W7 = (const float*)d_in[13];
    const float* b7 = (const float*)d_in[14];
    const float* W8 = (const float*)d_in[15];
    const float* b8 = (const float*)d_in[16];
    float* out = (float*)d_out;

    int batch = in_sizes[0] / 168;
    int grid = batch / ROWS_PER_CTA;

    prep_kernel<<<64, 256>>>(W1, b1, W2, b2, W3, b3, W4, b4,
                             W5, b5, W6, b6, W7, b7, W8, b8);

    cudaFuncSetAttribute(mlp_mma_kernel, cudaFuncAttributeMaxDynamicSharedMemorySize, SMEM_TOTAL);
    mlp_mma_kernel<<<grid, THREADS, SMEM_TOTAL>>>(x, out);
}